// round 1
// baseline (speedup 1.0000x reference)
#include <cuda_runtime.h>
#include <math.h>

// ---------------------------------------------------------------------------
// SpaceTimeLocalSelfAttention
// B=4, T=8, H=W=32, C=512, NH=8, DM=64, KT=4, KS=8
// 5 sequential windowed-attention passes (temporal recursion).
// Per pass: gather -> QKV gemm -> fused attention (online softmax) + residual
// ---------------------------------------------------------------------------

#define NWIN   64          // B * nb * nb = 4*4*4
#define SEQ    256         // KT * KS * KS
#define CH     512
#define NH     8
#define DM     64

// scratch (device globals; allocation-free rule)
__device__ float g_xb[NWIN * SEQ * CH];            // 8.4M floats
__device__ float g_q [NWIN * NH * SEQ * DM];
__device__ float g_k [NWIN * NH * SEQ * DM];
__device__ float g_v [NWIN * NH * SEQ * DM];

// ---------------------------------------------------------------------------
// Kernel 1: gather windowed input xb[n, s, c]
//   n = ((b*4 + by)*4 + bx), s = ((f*8 + ry)*8 + rx)
//   pass 0: frames f=0..3 from x[:,0:4]
//   pass p: f=0..2 from outbuf frames p+f, f=3 from x frame p+3
// ---------------------------------------------------------------------------
__global__ void gather_kernel(const float* __restrict__ x,
                              const float* __restrict__ outbuf,
                              int pass)
{
    int idx = blockIdx.x * blockDim.x + threadIdx.x;      // float4 index
    if (idx >= (NWIN * SEQ * CH) / 4) return;
    int e = idx * 4;
    int c = e & (CH - 1);
    int s = (e >> 9) & (SEQ - 1);
    int n = e >> 17;
    int f  = s >> 6;
    int ry = (s >> 3) & 7;
    int rx = s & 7;
    int b  = n >> 4;
    int by = (n >> 2) & 3;
    int bx = n & 3;
    int gr = by * 8 + ry;
    int gc = bx * 8 + rx;

    const float* src;
    if (pass == 0) {
        src = x + (((((size_t)b * 8 + f) * 32 + gr) * 32 + gc) * CH + c);
    } else if (f < 3) {
        src = outbuf + (((((size_t)b * 8 + (pass + f)) * 32 + gr) * 32 + gc) * CH + c);
    } else {
        src = x + (((((size_t)b * 8 + (pass + 3)) * 32 + gr) * 32 + gc) * CH + c);
    }
    *(float4*)(g_xb + e) = *(const float4*)src;
}

// ---------------------------------------------------------------------------
// Kernel 2: QKV projection.
//   q[n,h,s,d] = sum_c xb[n,s,c] * Wq[h,c,d] + bq[h,d]   (same for k, v)
//   GEMM M=16384 (n*256+s), K=512, per-head 64 output cols.
//   Block = (head h, 64-row tile). A tile reused for all three weights.
// ---------------------------------------------------------------------------
__global__ __launch_bounds__(256) void qkv_kernel(
    const float* __restrict__ Wq, const float* __restrict__ Wk,
    const float* __restrict__ Wv,
    const float* __restrict__ bq, const float* __restrict__ bk,
    const float* __restrict__ bv)
{
    const int h  = blockIdx.x;         // 0..7
    const int m0 = blockIdx.y * 64;    // row tile base (m = n*256 + s)

    __shared__ float As[16][64];       // A transposed: As[k][m]
    __shared__ float Bs[3][16][64];    // Bq, Bk, Bv: Bs[w][k][d]

    const int tid = threadIdx.x;
    const int tx = tid & 15;           // output col group (d = tx*4..)
    const int ty = tid >> 4;           // output row group (m = m0+ty*4..)

    float accq[4][4], acck[4][4], accv[4][4];
#pragma unroll
    for (int i = 0; i < 4; i++)
#pragma unroll
        for (int j = 0; j < 4; j++) { accq[i][j] = 0.f; acck[i][j] = 0.f; accv[i][j] = 0.f; }

    const float* wq = Wq + (size_t)h * CH * DM;
    const float* wk = Wk + (size_t)h * CH * DM;
    const float* wv = Wv + (size_t)h * CH * DM;

    const int ar  = tid >> 2;          // A load row 0..63
    const int ac4 = (tid & 3) * 4;     // A load col group
    const int br  = tid >> 4;          // B load row 0..15
    const int bc  = (tid & 15) * 4;    // B load col group

    for (int k0 = 0; k0 < CH; k0 += 16) {
        float4 a = *(const float4*)(g_xb + (size_t)(m0 + ar) * CH + k0 + ac4);
        As[ac4 + 0][ar] = a.x;
        As[ac4 + 1][ar] = a.y;
        As[ac4 + 2][ar] = a.z;
        As[ac4 + 3][ar] = a.w;
        *(float4*)&Bs[0][br][bc] = *(const float4*)(wq + (size_t)(k0 + br) * DM + bc);
        *(float4*)&Bs[1][br][bc] = *(const float4*)(wk + (size_t)(k0 + br) * DM + bc);
        *(float4*)&Bs[2][br][bc] = *(const float4*)(wv + (size_t)(k0 + br) * DM + bc);
        __syncthreads();

#pragma unroll
        for (int kk = 0; kk < 16; kk++) {
            float4 av = *(const float4*)&As[kk][ty * 4];
            float4 q4 = *(const float4*)&Bs[0][kk][tx * 4];
            float4 k4 = *(const float4*)&Bs[1][kk][tx * 4];
            float4 v4 = *(const float4*)&Bs[2][kk][tx * 4];
            float aa[4] = { av.x, av.y, av.z, av.w };
            float qq[4] = { q4.x, q4.y, q4.z, q4.w };
            float kkv[4] = { k4.x, k4.y, k4.z, k4.w };
            float vv[4] = { v4.x, v4.y, v4.z, v4.w };
#pragma unroll
            for (int i = 0; i < 4; i++)
#pragma unroll
                for (int j = 0; j < 4; j++) {
                    accq[i][j] += aa[i] * qq[j];
                    acck[i][j] += aa[i] * kkv[j];
                    accv[i][j] += aa[i] * vv[j];
                }
        }
        __syncthreads();
    }

    float bqv[4], bkv[4], bvv[4];
#pragma unroll
    for (int j = 0; j < 4; j++) {
        bqv[j] = bq[h * DM + tx * 4 + j];
        bkv[j] = bk[h * DM + tx * 4 + j];
        bvv[j] = bv[h * DM + tx * 4 + j];
    }

#pragma unroll
    for (int i = 0; i < 4; i++) {
        int m = m0 + ty * 4 + i;
        int n = m >> 8;
        int s = m & 255;
        size_t base = (size_t)n * (NH * SEQ * DM) + (size_t)h * (SEQ * DM) + (size_t)s * DM + tx * 4;
        float4 rq, rk, rv;
        rq.x = accq[i][0] + bqv[0]; rq.y = accq[i][1] + bqv[1];
        rq.z = accq[i][2] + bqv[2]; rq.w = accq[i][3] + bqv[3];
        rk.x = acck[i][0] + bkv[0]; rk.y = acck[i][1] + bkv[1];
        rk.z = acck[i][2] + bkv[2]; rk.w = acck[i][3] + bkv[3];
        rv.x = accv[i][0] + bvv[0]; rv.y = accv[i][1] + bvv[1];
        rv.z = accv[i][2] + bvv[2]; rv.w = accv[i][3] + bvv[3];
        *(float4*)(g_q + base) = rq;
        *(float4*)(g_k + base) = rk;
        *(float4*)(g_v + base) = rv;
    }
}

// ---------------------------------------------------------------------------
// Kernel 3: attention per (n, h) + residual + scatter to output layout.
//   One block per (n,h), 256 threads, one query row per thread.
//   K and V resident in 128 KB dynamic smem; online softmax in registers.
// ---------------------------------------------------------------------------
__global__ __launch_bounds__(256, 1) void attn_kernel(float* __restrict__ outbuf, int pass)
{
    const int n = blockIdx.x >> 3;
    const int h = blockIdx.x & 7;

    extern __shared__ float sm[];
    float* Ks = sm;                  // 256*64
    float* Vs = sm + SEQ * DM;       // 256*64

    const size_t head_base = ((size_t)n * NH + h) * SEQ * DM;
    const float4* kg = (const float4*)(g_k + head_base);
    const float4* vg = (const float4*)(g_v + head_base);
    for (int i = threadIdx.x; i < (SEQ * DM) / 4; i += 256) {
        ((float4*)Ks)[i] = kg[i];
        ((float4*)Vs)[i] = vg[i];
    }
    __syncthreads();

    const int s = threadIdx.x;
    const float4* qg = (const float4*)(g_q + head_base + (size_t)s * DM);

    float Q[DM];
#pragma unroll
    for (int i = 0; i < 16; i++) {
        float4 t4 = qg[i];
        Q[4 * i + 0] = t4.x; Q[4 * i + 1] = t4.y;
        Q[4 * i + 2] = t4.z; Q[4 * i + 3] = t4.w;
    }

    float o[DM];
#pragma unroll
    for (int i = 0; i < DM; i++) o[i] = 0.f;
    float mx = -1e30f, l = 0.f;

    for (int t = 0; t < SEQ; t++) {
        const float4* kr = (const float4*)(Ks + t * DM);
        float dot = 0.f;
#pragma unroll
        for (int i = 0; i < 16; i++) {
            float4 kv = kr[i];
            dot += Q[4 * i + 0] * kv.x + Q[4 * i + 1] * kv.y
                 + Q[4 * i + 2] * kv.z + Q[4 * i + 3] * kv.w;
        }
        float sc = dot * 0.125f;     // 1/sqrt(64)
        if (sc > mx) {
            float corr = __expf(mx - sc);
            mx = sc;
            l *= corr;
#pragma unroll
            for (int i = 0; i < DM; i++) o[i] *= corr;
        }
        float p = __expf(sc - mx);
        l += p;
        const float4* vr = (const float4*)(Vs + t * DM);
#pragma unroll
        for (int i = 0; i < 16; i++) {
            float4 vv = vr[i];
            o[4 * i + 0] += p * vv.x; o[4 * i + 1] += p * vv.y;
            o[4 * i + 2] += p * vv.z; o[4 * i + 3] += p * vv.w;
        }
    }

    float inv = 1.f / l;

    // scatter: s -> (f, ry, rx); n -> (b, by, bx); frame = pass + f (pass 0: f)
    int f  = s >> 6;
    int ry = (s >> 3) & 7;
    int rx = s & 7;
    int b  = n >> 4;
    int by = (n >> 2) & 3;
    int bx = n & 3;
    int gr = by * 8 + ry;
    int gc = bx * 8 + rx;
    int frame = pass + f;            // pass 0 => frames 0..3

    float* dst = outbuf + (((((size_t)b * 8 + frame) * 32 + gr) * 32 + gc) * CH) + h * DM;
    const float* res = g_xb + ((size_t)n * SEQ + s) * CH + h * DM;

#pragma unroll
    for (int i = 0; i < 16; i++) {
        float4 r = ((const float4*)res)[i];
        float4 w;
        w.x = o[4 * i + 0] * inv + r.x;
        w.y = o[4 * i + 1] * inv + r.y;
        w.z = o[4 * i + 2] * inv + r.z;
        w.w = o[4 * i + 3] * inv + r.w;
        ((float4*)dst)[i] = w;
    }
}

// ---------------------------------------------------------------------------
extern "C" void kernel_launch(void* const* d_in, const int* in_sizes, int n_in,
                              void* d_out, int out_size)
{
    const float* x  = (const float*)d_in[0];
    const float* Wq = (const float*)d_in[1];
    const float* Wk = (const float*)d_in[2];
    const float* Wv = (const float*)d_in[3];
    const float* bq = (const float*)d_in[4];
    const float* bk = (const float*)d_in[5];
    const float* bv = (const float*)d_in[6];
    float* out = (float*)d_out;

    cudaFuncSetAttribute(attn_kernel, cudaFuncAttributeMaxDynamicSharedMemorySize,
                         2 * SEQ * DM * (int)sizeof(float));

    const int gather_blocks = (NWIN * SEQ * CH / 4 + 255) / 256;

    for (int pass = 0; pass <= 4; pass++) {
        gather_kernel<<<gather_blocks, 256>>>(x, out, pass);
        dim3 gq(NH, (NWIN * SEQ) / 64);
        qkv_kernel<<<gq, 256>>>(Wq, Wk, Wv, bq, bk, bv);
        attn_kernel<<<NWIN * NH, 256, 2 * SEQ * DM * (int)sizeof(float)>>>(out, pass);
    }
}

// round 3
// speedup vs baseline: 1.6609x; 1.6609x over previous
#include <cuda_runtime.h>
#include <math.h>
#include <stdint.h>

// ---------------------------------------------------------------------------
// SpaceTimeLocalSelfAttention — R3: QKV projection on mma.sync tf32 (sm_100-safe)
// B=4, T=8, H=W=32, C=512, NH=8, DM=64, KT=4, KS=8
// ---------------------------------------------------------------------------

#define NWIN   64
#define SEQ    256
#define CH     512
#define NH     8
#define DM     64
#define NTOT   (3 * NH * DM)      // 1536 fused QKV output columns

__device__ float g_xb[NWIN * SEQ * CH];
__device__ float g_q [NWIN * NH * SEQ * DM];
__device__ float g_k [NWIN * NH * SEQ * DM];
__device__ float g_v [NWIN * NH * SEQ * DM];
__device__ float g_wt[NTOT * CH];   // B^T: row j=(w*NH+h)*64+n, col k. tf32-rounded.

__device__ __forceinline__ float tf32r(float x) {
    uint32_t u;
    asm("cvt.rna.tf32.f32 %0, %1;" : "=r"(u) : "f"(x));
    return __uint_as_float(u);
}

__device__ __forceinline__ void mma_tf32(float& c0, float& c1, float& c2, float& c3,
                                         uint32_t a0, uint32_t a1, uint32_t a2, uint32_t a3,
                                         uint32_t b0, uint32_t b1)
{
    asm volatile(
        "mma.sync.aligned.m16n8k8.row.col.f32.tf32.tf32.f32 "
        "{%0,%1,%2,%3}, {%4,%5,%6,%7}, {%8,%9}, {%0,%1,%2,%3};"
        : "+f"(c0), "+f"(c1), "+f"(c2), "+f"(c3)
        : "r"(a0), "r"(a1), "r"(a2), "r"(a3), "r"(b0), "r"(b1));
}

// ---------------------------------------------------------------------------
// Kernel 0 (once): transpose + tf32-round weights -> g_wt[(w*NH+h)*64+n][k]
// ---------------------------------------------------------------------------
__global__ void wtrans_kernel(const float* __restrict__ Wq,
                              const float* __restrict__ Wk,
                              const float* __restrict__ Wv)
{
    int idx = blockIdx.x * blockDim.x + threadIdx.x;
    if (idx >= 3 * NH * CH * DM) return;
    int n = idx & (DM - 1);
    int k = (idx >> 6) & (CH - 1);
    int h = (idx >> 15) & (NH - 1);
    int w = idx >> 18;
    const float* W = (w == 0) ? Wq : (w == 1) ? Wk : Wv;
    float v = W[((size_t)h * CH + k) * DM + n];
    g_wt[(((size_t)(w * NH + h) * DM + n) * CH) + k] = tf32r(v);
}

// ---------------------------------------------------------------------------
// Kernel 1: gather windowed input xb[n, s, c]
// ---------------------------------------------------------------------------
__global__ void gather_kernel(const float* __restrict__ x,
                              const float* __restrict__ outbuf,
                              int pass)
{
    int idx = blockIdx.x * blockDim.x + threadIdx.x;
    if (idx >= (NWIN * SEQ * CH) / 4) return;
    int e = idx * 4;
    int c = e & (CH - 1);
    int s = (e >> 9) & (SEQ - 1);
    int n = e >> 17;
    int f  = s >> 6;
    int ry = (s >> 3) & 7;
    int rx = s & 7;
    int b  = n >> 4;
    int by = (n >> 2) & 3;
    int bx = n & 3;
    int gr = by * 8 + ry;
    int gc = bx * 8 + rx;

    const float* src;
    if (pass == 0) {
        src = x + (((((size_t)b * 8 + f) * 32 + gr) * 32 + gc) * CH + c);
    } else if (f < 3) {
        src = outbuf + (((((size_t)b * 8 + (pass + f)) * 32 + gr) * 32 + gc) * CH + c);
    } else {
        src = x + (((((size_t)b * 8 + (pass + 3)) * 32 + gr) * 32 + gc) * CH + c);
    }
    *(float4*)(g_xb + e) = *(const float4*)src;
}

// ---------------------------------------------------------------------------
// Kernel 2: fused QKV GEMM via mma.sync tf32.
//   C[16384, 1536] = A[16384, 512] x B[512, 1536]  (B given as B^T rows)
//   Block 128x128, 8 warps (4 M x 2 N), warp tile 32x64, K-chunk 32.
// ---------------------------------------------------------------------------
#define AP 36   // smem row pitch (32 + 4 pad), keeps 16B alignment, kills conflicts

__global__ __launch_bounds__(256) void qkv_mma_kernel(
    const float* __restrict__ bq, const float* __restrict__ bk,
    const float* __restrict__ bv)
{
    const int m0 = blockIdx.x * 128;
    const int n0 = blockIdx.y * 128;

    __shared__ float As[128 * AP];
    __shared__ float Bs[128 * AP];

    const int tid = threadIdx.x;
    const int wid = tid >> 5;
    const int lane = tid & 31;
    const int gid = lane >> 2;       // groupID
    const int tig = lane & 3;        // threadID_in_group
    const int mwarp = wid & 3;       // 0..3
    const int nwarp = wid >> 2;      // 0..1

    float c[2][8][4];
#pragma unroll
    for (int mt = 0; mt < 2; mt++)
#pragma unroll
        for (int nt = 0; nt < 8; nt++)
#pragma unroll
            for (int r = 0; r < 4; r++) c[mt][nt][r] = 0.f;

    for (int kc = 0; kc < CH; kc += 32) {
        // stage A tile (128x32) and B tile (128 rows of B^T x 32)
#pragma unroll
        for (int i = 0; i < 4; i++) {
            int chunk = tid + 256 * i;           // 0..1023
            int row = chunk >> 3;
            int kg = (chunk & 7) * 4;
            float4 a = *(const float4*)(g_xb + (size_t)(m0 + row) * CH + kc + kg);
            a.x = tf32r(a.x); a.y = tf32r(a.y); a.z = tf32r(a.z); a.w = tf32r(a.w);
            *(float4*)(As + row * AP + kg) = a;
            float4 b = *(const float4*)(g_wt + (size_t)(n0 + row) * CH + kc + kg);
            *(float4*)(Bs + row * AP + kg) = b;
        }
        __syncthreads();

#pragma unroll
        for (int k8 = 0; k8 < 4; k8++) {
            const int kk = k8 * 8;
            uint32_t af[2][4];
#pragma unroll
            for (int mt = 0; mt < 2; mt++) {
                int rb = mwarp * 32 + mt * 16;
                af[mt][0] = __float_as_uint(As[(rb + gid)     * AP + kk + tig]);
                af[mt][1] = __float_as_uint(As[(rb + gid + 8) * AP + kk + tig]);
                af[mt][2] = __float_as_uint(As[(rb + gid)     * AP + kk + tig + 4]);
                af[mt][3] = __float_as_uint(As[(rb + gid + 8) * AP + kk + tig + 4]);
            }
#pragma unroll
            for (int nt = 0; nt < 8; nt++) {
                int nb = nwarp * 64 + nt * 8 + gid;
                uint32_t b0 = __float_as_uint(Bs[nb * AP + kk + tig]);
                uint32_t b1 = __float_as_uint(Bs[nb * AP + kk + tig + 4]);
#pragma unroll
                for (int mt = 0; mt < 2; mt++)
                    mma_tf32(c[mt][nt][0], c[mt][nt][1], c[mt][nt][2], c[mt][nt][3],
                             af[mt][0], af[mt][1], af[mt][2], af[mt][3], b0, b1);
            }
        }
        __syncthreads();
    }

    // Epilogue: this warp's 64 columns live in a single (w,h) chunk.
    const int j = blockIdx.y * 2 + nwarp;     // 0..23  = w*8 + h
    const int wsel = j >> 3;
    const int h = j & 7;
    const float* bias = ((wsel == 0) ? bq : (wsel == 1) ? bk : bv) + h * DM;
    float* outp = (wsel == 0) ? g_q : (wsel == 1) ? g_k : g_v;

#pragma unroll
    for (int mt = 0; mt < 2; mt++) {
#pragma unroll
        for (int half = 0; half < 2; half++) {    // c0/c1 vs c2/c3 (row, row+8)
            int m = m0 + mwarp * 32 + mt * 16 + gid + half * 8;
            int n = m >> 8;
            int s = m & 255;
            float* rowp = outp + (((size_t)n * NH + h) * SEQ + s) * DM;
#pragma unroll
            for (int nt = 0; nt < 8; nt++) {
                int d = nt * 8 + 2 * tig;
                float2 o;
                o.x = c[mt][nt][half * 2 + 0] + bias[d];
                o.y = c[mt][nt][half * 2 + 1] + bias[d + 1];
                *(float2*)(rowp + d) = o;
            }
        }
    }
}

// ---------------------------------------------------------------------------
// Kernel 3: attention per (n, h) + residual + scatter (fp32).
// ---------------------------------------------------------------------------
__global__ __launch_bounds__(256, 1) void attn_kernel(float* __restrict__ outbuf, int pass)
{
    const int n = blockIdx.x >> 3;
    const int h = blockIdx.x & 7;

    extern __shared__ float sm[];
    float* Ks = sm;
    float* Vs = sm + SEQ * DM;

    const size_t head_base = ((size_t)n * NH + h) * SEQ * DM;
    const float4* kg = (const float4*)(g_k + head_base);
    const float4* vg = (const float4*)(g_v + head_base);
    for (int i = threadIdx.x; i < (SEQ * DM) / 4; i += 256) {
        ((float4*)Ks)[i] = kg[i];
        ((float4*)Vs)[i] = vg[i];
    }
    __syncthreads();

    const int s = threadIdx.x;
    const float4* qg = (const float4*)(g_q + head_base + (size_t)s * DM);

    float Q[DM];
#pragma unroll
    for (int i = 0; i < 16; i++) {
        float4 t4 = qg[i];
        Q[4 * i + 0] = t4.x; Q[4 * i + 1] = t4.y;
        Q[4 * i + 2] = t4.z; Q[4 * i + 3] = t4.w;
    }

    float o[DM];
#pragma unroll
    for (int i = 0; i < DM; i++) o[i] = 0.f;
    float mx = -1e30f, l = 0.f;

    for (int t = 0; t < SEQ; t++) {
        const float4* kr = (const float4*)(Ks + t * DM);
        float dot = 0.f;
#pragma unroll
        for (int i = 0; i < 16; i++) {
            float4 kv = kr[i];
            dot += Q[4 * i + 0] * kv.x + Q[4 * i + 1] * kv.y
                 + Q[4 * i + 2] * kv.z + Q[4 * i + 3] * kv.w;
        }
        float sc = dot * 0.125f;
        if (sc > mx) {
            float corr = __expf(mx - sc);
            mx = sc;
            l *= corr;
#pragma unroll
            for (int i = 0; i < DM; i++) o[i] *= corr;
        }
        float p = __expf(sc - mx);
        l += p;
        const float4* vr = (const float4*)(Vs + t * DM);
#pragma unroll
        for (int i = 0; i < 16; i++) {
            float4 vv = vr[i];
            o[4 * i + 0] += p * vv.x; o[4 * i + 1] += p * vv.y;
            o[4 * i + 2] += p * vv.z; o[4 * i + 3] += p * vv.w;
        }
    }

    float inv = 1.f / l;

    int f  = s >> 6;
    int ry = (s >> 3) & 7;
    int rx = s & 7;
    int b  = n >> 4;
    int by = (n >> 2) & 3;
    int bx = n & 3;
    int gr = by * 8 + ry;
    int gc = bx * 8 + rx;
    int frame = pass + f;

    float* dst = outbuf + (((((size_t)b * 8 + frame) * 32 + gr) * 32 + gc) * CH) + h * DM;
    const float* res = g_xb + ((size_t)n * SEQ + s) * CH + h * DM;

#pragma unroll
    for (int i = 0; i < 16; i++) {
        float4 r = ((const float4*)res)[i];
        float4 w;
        w.x = o[4 * i + 0] * inv + r.x;
        w.y = o[4 * i + 1] * inv + r.y;
        w.z = o[4 * i + 2] * inv + r.z;
        w.w = o[4 * i + 3] * inv + r.w;
        ((float4*)dst)[i] = w;
    }
}

// ---------------------------------------------------------------------------
extern "C" void kernel_launch(void* const* d_in, const int* in_sizes, int n_in,
                              void* d_out, int out_size)
{
    const float* x  = (const float*)d_in[0];
    const float* Wq = (const float*)d_in[1];
    const float* Wk = (const float*)d_in[2];
    const float* Wv = (const float*)d_in[3];
    const float* bq = (const float*)d_in[4];
    const float* bk = (const float*)d_in[5];
    const float* bv = (const float*)d_in[6];
    float* out = (float*)d_out;

    cudaFuncSetAttribute(attn_kernel, cudaFuncAttributeMaxDynamicSharedMemorySize,
                         2 * SEQ * DM * (int)sizeof(float));

    wtrans_kernel<<<(3 * NH * CH * DM + 255) / 256, 256>>>(Wq, Wk, Wv);

    const int gather_blocks = (NWIN * SEQ * CH / 4 + 255) / 256;

    for (int pass = 0; pass <= 4; pass++) {
        gather_kernel<<<gather_blocks, 256>>>(x, out, pass);
        dim3 gq((NWIN * SEQ) / 128, NTOT / 128);
        qkv_mma_kernel<<<gq, 256>>>(bq, bk, bv);
        attn_kernel<<<NWIN * NH, 256, 2 * SEQ * DM * (int)sizeof(float)>>>(out, pass);
    }
}

// round 4
// speedup vs baseline: 2.9327x; 1.7658x over previous
#include <cuda_runtime.h>
#include <math.h>
#include <stdint.h>

// ---------------------------------------------------------------------------
// SpaceTimeLocalSelfAttention — R4: QKV + attention both on mma.sync tf32
// B=4, T=8, H=W=32, C=512, NH=8, DM=64, KT=4, KS=8
// ---------------------------------------------------------------------------

#define NWIN   64
#define SEQ    256
#define CH     512
#define NH     8
#define DM     64
#define NTOT   (3 * NH * DM)

__device__ float g_xb[NWIN * SEQ * CH];
__device__ float g_q [NWIN * NH * SEQ * DM];
__device__ float g_k [NWIN * NH * SEQ * DM];
__device__ float g_v [NWIN * NH * SEQ * DM];
__device__ float g_wt[NTOT * CH];

__device__ __forceinline__ float tf32r(float x) {
    uint32_t u;
    asm("cvt.rna.tf32.f32 %0, %1;" : "=r"(u) : "f"(x));
    return __uint_as_float(u);
}

__device__ __forceinline__ void mma_tf32(float& c0, float& c1, float& c2, float& c3,
                                         uint32_t a0, uint32_t a1, uint32_t a2, uint32_t a3,
                                         uint32_t b0, uint32_t b1)
{
    asm volatile(
        "mma.sync.aligned.m16n8k8.row.col.f32.tf32.tf32.f32 "
        "{%0,%1,%2,%3}, {%4,%5,%6,%7}, {%8,%9}, {%0,%1,%2,%3};"
        : "+f"(c0), "+f"(c1), "+f"(c2), "+f"(c3)
        : "r"(a0), "r"(a1), "r"(a2), "r"(a3), "r"(b0), "r"(b1));
}

// ---------------------------------------------------------------------------
__global__ void wtrans_kernel(const float* __restrict__ Wq,
                              const float* __restrict__ Wk,
                              const float* __restrict__ Wv)
{
    int idx = blockIdx.x * blockDim.x + threadIdx.x;
    if (idx >= 3 * NH * CH * DM) return;
    int n = idx & (DM - 1);
    int k = (idx >> 6) & (CH - 1);
    int h = (idx >> 15) & (NH - 1);
    int w = idx >> 18;
    const float* W = (w == 0) ? Wq : (w == 1) ? Wk : Wv;
    float v = W[((size_t)h * CH + k) * DM + n];
    g_wt[(((size_t)(w * NH + h) * DM + n) * CH) + k] = tf32r(v);
}

// ---------------------------------------------------------------------------
__global__ void gather_kernel(const float* __restrict__ x,
                              const float* __restrict__ outbuf,
                              int pass)
{
    int idx = blockIdx.x * blockDim.x + threadIdx.x;
    if (idx >= (NWIN * SEQ * CH) / 4) return;
    int e = idx * 4;
    int c = e & (CH - 1);
    int s = (e >> 9) & (SEQ - 1);
    int n = e >> 17;
    int f  = s >> 6;
    int ry = (s >> 3) & 7;
    int rx = s & 7;
    int b  = n >> 4;
    int by = (n >> 2) & 3;
    int bx = n & 3;
    int gr = by * 8 + ry;
    int gc = bx * 8 + rx;

    const float* src;
    if (pass == 0) {
        src = x + (((((size_t)b * 8 + f) * 32 + gr) * 32 + gc) * CH + c);
    } else if (f < 3) {
        src = outbuf + (((((size_t)b * 8 + (pass + f)) * 32 + gr) * 32 + gc) * CH + c);
    } else {
        src = x + (((((size_t)b * 8 + (pass + 3)) * 32 + gr) * 32 + gc) * CH + c);
    }
    *(float4*)(g_xb + e) = *(const float4*)src;
}

// ---------------------------------------------------------------------------
// QKV GEMM (mma.sync tf32) — unchanged from R3.
// ---------------------------------------------------------------------------
#define AP 36

__global__ __launch_bounds__(256) void qkv_mma_kernel(
    const float* __restrict__ bq, const float* __restrict__ bk,
    const float* __restrict__ bv)
{
    const int m0 = blockIdx.x * 128;
    const int n0 = blockIdx.y * 128;

    __shared__ float As[128 * AP];
    __shared__ float Bs[128 * AP];

    const int tid = threadIdx.x;
    const int wid = tid >> 5;
    const int lane = tid & 31;
    const int gid = lane >> 2;
    const int tig = lane & 3;
    const int mwarp = wid & 3;
    const int nwarp = wid >> 2;

    float c[2][8][4];
#pragma unroll
    for (int mt = 0; mt < 2; mt++)
#pragma unroll
        for (int nt = 0; nt < 8; nt++)
#pragma unroll
            for (int r = 0; r < 4; r++) c[mt][nt][r] = 0.f;

    for (int kc = 0; kc < CH; kc += 32) {
#pragma unroll
        for (int i = 0; i < 4; i++) {
            int chunk = tid + 256 * i;
            int row = chunk >> 3;
            int kg = (chunk & 7) * 4;
            float4 a = *(const float4*)(g_xb + (size_t)(m0 + row) * CH + kc + kg);
            a.x = tf32r(a.x); a.y = tf32r(a.y); a.z = tf32r(a.z); a.w = tf32r(a.w);
            *(float4*)(As + row * AP + kg) = a;
            float4 b = *(const float4*)(g_wt + (size_t)(n0 + row) * CH + kc + kg);
            *(float4*)(Bs + row * AP + kg) = b;
        }
        __syncthreads();

#pragma unroll
        for (int k8 = 0; k8 < 4; k8++) {
            const int kk = k8 * 8;
            uint32_t af[2][4];
#pragma unroll
            for (int mt = 0; mt < 2; mt++) {
                int rb = mwarp * 32 + mt * 16;
                af[mt][0] = __float_as_uint(As[(rb + gid)     * AP + kk + tig]);
                af[mt][1] = __float_as_uint(As[(rb + gid + 8) * AP + kk + tig]);
                af[mt][2] = __float_as_uint(As[(rb + gid)     * AP + kk + tig + 4]);
                af[mt][3] = __float_as_uint(As[(rb + gid + 8) * AP + kk + tig + 4]);
            }
#pragma unroll
            for (int nt = 0; nt < 8; nt++) {
                int nb = nwarp * 64 + nt * 8 + gid;
                uint32_t b0 = __float_as_uint(Bs[nb * AP + kk + tig]);
                uint32_t b1 = __float_as_uint(Bs[nb * AP + kk + tig + 4]);
#pragma unroll
                for (int mt = 0; mt < 2; mt++)
                    mma_tf32(c[mt][nt][0], c[mt][nt][1], c[mt][nt][2], c[mt][nt][3],
                             af[mt][0], af[mt][1], af[mt][2], af[mt][3], b0, b1);
            }
        }
        __syncthreads();
    }

    const int j = blockIdx.y * 2 + nwarp;
    const int wsel = j >> 3;
    const int h = j & 7;
    const float* bias = ((wsel == 0) ? bq : (wsel == 1) ? bk : bv) + h * DM;
    float* outp = (wsel == 0) ? g_q : (wsel == 1) ? g_k : g_v;

#pragma unroll
    for (int mt = 0; mt < 2; mt++) {
#pragma unroll
        for (int half = 0; half < 2; half++) {
            int m = m0 + mwarp * 32 + mt * 16 + gid + half * 8;
            int n = m >> 8;
            int s = m & 255;
            float* rowp = outp + (((size_t)n * NH + h) * SEQ + s) * DM;
#pragma unroll
            for (int nt = 0; nt < 8; nt++) {
                int d = nt * 8 + 2 * tig;
                float2 o;
                o.x = c[mt][nt][half * 2 + 0] + bias[d];
                o.y = c[mt][nt][half * 2 + 1] + bias[d + 1];
                *(float2*)(rowp + d) = o;
            }
        }
    }
}

// ---------------------------------------------------------------------------
// R4: tensor-core flash attention per (n, h).
//   8 warps x 32 query rows. smem: K[256x68] + V[256x68] + Q/P slab[256x68].
//   Mainloop has no __syncthreads (K/V read-only, P slab warp-private).
// ---------------------------------------------------------------------------
#define KP 68   // smem pitch (64 + 4)

__global__ __launch_bounds__(256, 1) void attn_tc_kernel(float* __restrict__ outbuf, int pass)
{
    const int n = blockIdx.x >> 3;
    const int h = blockIdx.x & 7;

    extern __shared__ float sm[];
    float* Ks = sm;
    float* Vs = sm + SEQ * KP;
    float* Pq = sm + 2 * SEQ * KP;    // Q staging, then per-warp P slabs

    const int tid = threadIdx.x;
    const int wid = tid >> 5;
    const int lane = tid & 31;
    const int gid = lane >> 2;
    const int tig = lane & 3;
    const int wq = wid * 32;          // this warp's query row base

    const size_t head_base = ((size_t)n * NH + h) * SEQ * DM;

    // stage K, V, Q (tf32-rounded; Q pre-scaled by 1/8 = exact pow2)
    for (int i = tid; i < SEQ * (DM / 4); i += 256) {
        int row = i >> 4;
        int cg = (i & 15) * 4;
        float4 k4 = *(const float4*)(g_k + head_base + (size_t)row * DM + cg);
        k4.x = tf32r(k4.x); k4.y = tf32r(k4.y); k4.z = tf32r(k4.z); k4.w = tf32r(k4.w);
        *(float4*)(Ks + row * KP + cg) = k4;
        float4 v4 = *(const float4*)(g_v + head_base + (size_t)row * DM + cg);
        v4.x = tf32r(v4.x); v4.y = tf32r(v4.y); v4.z = tf32r(v4.z); v4.w = tf32r(v4.w);
        *(float4*)(Vs + row * KP + cg) = v4;
        float4 q4 = *(const float4*)(g_q + head_base + (size_t)row * DM + cg);
        q4.x = tf32r(q4.x * 0.125f); q4.y = tf32r(q4.y * 0.125f);
        q4.z = tf32r(q4.z * 0.125f); q4.w = tf32r(q4.w * 0.125f);
        *(float4*)(Pq + row * KP + cg) = q4;
    }
    __syncthreads();

    // Q fragments (held in registers for the whole kernel)
    uint32_t qf[2][8][4];
#pragma unroll
    for (int mt = 0; mt < 2; mt++) {
        int rb = wq + mt * 16;
#pragma unroll
        for (int kt = 0; kt < 8; kt++) {
            int cc = kt * 8;
            qf[mt][kt][0] = __float_as_uint(Pq[(rb + gid)     * KP + cc + tig]);
            qf[mt][kt][1] = __float_as_uint(Pq[(rb + gid + 8) * KP + cc + tig]);
            qf[mt][kt][2] = __float_as_uint(Pq[(rb + gid)     * KP + cc + tig + 4]);
            qf[mt][kt][3] = __float_as_uint(Pq[(rb + gid + 8) * KP + cc + tig + 4]);
        }
    }
    __syncwarp();

    float o[2][8][4];
#pragma unroll
    for (int mt = 0; mt < 2; mt++)
#pragma unroll
        for (int nt = 0; nt < 8; nt++)
#pragma unroll
            for (int r = 0; r < 4; r++) o[mt][nt][r] = 0.f;

    float mrun[4], lrun[4];
#pragma unroll
    for (int z = 0; z < 4; z++) { mrun[z] = -1e30f; lrun[z] = 0.f; }

    for (int kb = 0; kb < 4; kb++) {
        const int kbase = kb * 64;

        // S = Q * K^T  (32 x 64 per warp)
        float s[2][8][4];
#pragma unroll
        for (int mt = 0; mt < 2; mt++)
#pragma unroll
            for (int nt = 0; nt < 8; nt++)
#pragma unroll
                for (int r = 0; r < 4; r++) s[mt][nt][r] = 0.f;

#pragma unroll
        for (int kt = 0; kt < 8; kt++) {
            const int cc = kt * 8;
#pragma unroll
            for (int nt = 0; nt < 8; nt++) {
                int key = kbase + nt * 8 + gid;
                uint32_t b0 = __float_as_uint(Ks[key * KP + cc + tig]);
                uint32_t b1 = __float_as_uint(Ks[key * KP + cc + tig + 4]);
#pragma unroll
                for (int mt = 0; mt < 2; mt++)
                    mma_tf32(s[mt][nt][0], s[mt][nt][1], s[mt][nt][2], s[mt][nt][3],
                             qf[mt][kt][0], qf[mt][kt][1], qf[mt][kt][2], qf[mt][kt][3],
                             b0, b1);
            }
        }

        // online softmax: slot = mt*2 + hh (rows gid, gid+8 per m-tile)
        float mloc[4];
#pragma unroll
        for (int z = 0; z < 4; z++) mloc[z] = -1e30f;
#pragma unroll
        for (int mt = 0; mt < 2; mt++)
#pragma unroll
            for (int nt = 0; nt < 8; nt++) {
                mloc[mt * 2 + 0] = fmaxf(mloc[mt * 2 + 0], fmaxf(s[mt][nt][0], s[mt][nt][1]));
                mloc[mt * 2 + 1] = fmaxf(mloc[mt * 2 + 1], fmaxf(s[mt][nt][2], s[mt][nt][3]));
            }
#pragma unroll
        for (int z = 0; z < 4; z++) {
            mloc[z] = fmaxf(mloc[z], __shfl_xor_sync(0xffffffffu, mloc[z], 1));
            mloc[z] = fmaxf(mloc[z], __shfl_xor_sync(0xffffffffu, mloc[z], 2));
        }
        float scale[4], lsum[4];
#pragma unroll
        for (int z = 0; z < 4; z++) {
            float mnew = fmaxf(mrun[z], mloc[z]);
            scale[z] = __expf(mrun[z] - mnew);
            mrun[z] = mnew;
            lsum[z] = 0.f;
        }
#pragma unroll
        for (int mt = 0; mt < 2; mt++)
#pragma unroll
            for (int nt = 0; nt < 8; nt++) {
                s[mt][nt][0] = __expf(s[mt][nt][0] - mrun[mt * 2 + 0]);
                s[mt][nt][1] = __expf(s[mt][nt][1] - mrun[mt * 2 + 0]);
                s[mt][nt][2] = __expf(s[mt][nt][2] - mrun[mt * 2 + 1]);
                s[mt][nt][3] = __expf(s[mt][nt][3] - mrun[mt * 2 + 1]);
                lsum[mt * 2 + 0] += s[mt][nt][0] + s[mt][nt][1];
                lsum[mt * 2 + 1] += s[mt][nt][2] + s[mt][nt][3];
            }
#pragma unroll
        for (int z = 0; z < 4; z++) {
            lsum[z] += __shfl_xor_sync(0xffffffffu, lsum[z], 1);
            lsum[z] += __shfl_xor_sync(0xffffffffu, lsum[z], 2);
            lrun[z] = lrun[z] * scale[z] + lsum[z];
        }
        // rescale O
#pragma unroll
        for (int mt = 0; mt < 2; mt++)
#pragma unroll
            for (int nt = 0; nt < 8; nt++) {
                o[mt][nt][0] *= scale[mt * 2 + 0];
                o[mt][nt][1] *= scale[mt * 2 + 0];
                o[mt][nt][2] *= scale[mt * 2 + 1];
                o[mt][nt][3] *= scale[mt * 2 + 1];
            }

        // P -> warp-private smem slab (tf32), then reload as A fragments
        __syncwarp();
#pragma unroll
        for (int mt = 0; mt < 2; mt++) {
            int rb = wq + mt * 16;
#pragma unroll
            for (int nt = 0; nt < 8; nt++) {
                int col = nt * 8 + 2 * tig;
                float2 p0, p1;
                p0.x = tf32r(s[mt][nt][0]); p0.y = tf32r(s[mt][nt][1]);
                p1.x = tf32r(s[mt][nt][2]); p1.y = tf32r(s[mt][nt][3]);
                *(float2*)(Pq + (rb + gid)     * KP + col) = p0;
                *(float2*)(Pq + (rb + gid + 8) * KP + col) = p1;
            }
        }
        __syncwarp();

        uint32_t pf[2][8][4];
#pragma unroll
        for (int mt = 0; mt < 2; mt++) {
            int rb = wq + mt * 16;
#pragma unroll
            for (int kt = 0; kt < 8; kt++) {
                int cc = kt * 8;
                pf[mt][kt][0] = __float_as_uint(Pq[(rb + gid)     * KP + cc + tig]);
                pf[mt][kt][1] = __float_as_uint(Pq[(rb + gid + 8) * KP + cc + tig]);
                pf[mt][kt][2] = __float_as_uint(Pq[(rb + gid)     * KP + cc + tig + 4]);
                pf[mt][kt][3] = __float_as_uint(Pq[(rb + gid + 8) * KP + cc + tig + 4]);
            }
        }

        // O += P * V
#pragma unroll
        for (int kt = 0; kt < 8; kt++) {
#pragma unroll
            for (int nt = 0; nt < 8; nt++) {
                int dmc = nt * 8 + gid;
                uint32_t b0 = __float_as_uint(Vs[(kbase + kt * 8 + tig)     * KP + dmc]);
                uint32_t b1 = __float_as_uint(Vs[(kbase + kt * 8 + tig + 4) * KP + dmc]);
#pragma unroll
                for (int mt = 0; mt < 2; mt++)
                    mma_tf32(o[mt][nt][0], o[mt][nt][1], o[mt][nt][2], o[mt][nt][3],
                             pf[mt][kt][0], pf[mt][kt][1], pf[mt][kt][2], pf[mt][kt][3],
                             b0, b1);
            }
        }
    }

    // epilogue: normalize, residual, scatter
    float inv[4];
#pragma unroll
    for (int z = 0; z < 4; z++) inv[z] = 1.f / lrun[z];

    const int b  = n >> 4;
    const int by = (n >> 2) & 3;
    const int bx = n & 3;

#pragma unroll
    for (int mt = 0; mt < 2; mt++) {
#pragma unroll
        for (int hh = 0; hh < 2; hh++) {
            int q = wq + mt * 16 + gid + 8 * hh;
            int f  = q >> 6;
            int ry = (q >> 3) & 7;
            int rx = q & 7;
            int gr = by * 8 + ry;
            int gc = bx * 8 + rx;
            int frame = pass + f;
            float* dst = outbuf + (((((size_t)b * 8 + frame) * 32 + gr) * 32 + gc) * CH) + h * DM;
            const float* res = g_xb + ((size_t)n * SEQ + q) * CH + h * DM;
            float sc = inv[mt * 2 + hh];
#pragma unroll
            for (int nt = 0; nt < 8; nt++) {
                int d = nt * 8 + 2 * tig;
                float2 r = *(const float2*)(res + d);
                float2 ov;
                ov.x = o[mt][nt][2 * hh + 0] * sc + r.x;
                ov.y = o[mt][nt][2 * hh + 1] * sc + r.y;
                *(float2*)(dst + d) = ov;
            }
        }
    }
}

// ---------------------------------------------------------------------------
extern "C" void kernel_launch(void* const* d_in, const int* in_sizes, int n_in,
                              void* d_out, int out_size)
{
    const float* x  = (const float*)d_in[0];
    const float* Wq = (const float*)d_in[1];
    const float* Wk = (const float*)d_in[2];
    const float* Wv = (const float*)d_in[3];
    const float* bq = (const float*)d_in[4];
    const float* bk = (const float*)d_in[5];
    const float* bv = (const float*)d_in[6];
    float* out = (float*)d_out;

    const int attn_smem = 3 * SEQ * KP * (int)sizeof(float);   // 204 KB
    cudaFuncSetAttribute(attn_tc_kernel, cudaFuncAttributeMaxDynamicSharedMemorySize,
                         attn_smem);

    wtrans_kernel<<<(3 * NH * CH * DM + 255) / 256, 256>>>(Wq, Wk, Wv);

    const int gather_blocks = (NWIN * SEQ * CH / 4 + 255) / 256;

    for (int pass = 0; pass <= 4; pass++) {
        gather_kernel<<<gather_blocks, 256>>>(x, out, pass);
        dim3 gq((NWIN * SEQ) / 128, NTOT / 128);
        qkv_mma_kernel<<<gq, 256>>>(bq, bk, bv);
        attn_tc_kernel<<<NWIN * NH, 256, attn_smem>>>(out, pass);
    }
}

// round 5
// speedup vs baseline: 2.9982x; 1.0223x over previous
#include <cuda_runtime.h>
#include <math.h>
#include <stdint.h>

// ---------------------------------------------------------------------------
// SpaceTimeLocalSelfAttention — R5
//   QKV: tf32 mma.sync + cp.async double-buffered pipeline (2 CTA/SM)
//   Attention: tf32 mma.sync flash, 512 threads / 16 warps
// B=4, T=8, H=W=32, C=512, NH=8, DM=64, KT=4, KS=8
// ---------------------------------------------------------------------------

#define NWIN   64
#define SEQ    256
#define CH     512
#define NH     8
#define DM     64
#define NTOT   (3 * NH * DM)

__device__ float g_xb[NWIN * SEQ * CH];
__device__ float g_q [NWIN * NH * SEQ * DM];
__device__ float g_k [NWIN * NH * SEQ * DM];
__device__ float g_v [NWIN * NH * SEQ * DM];
__device__ float g_wt[NTOT * CH];

__device__ __forceinline__ float tf32r(float x) {
    uint32_t u;
    asm("cvt.rna.tf32.f32 %0, %1;" : "=r"(u) : "f"(x));
    return __uint_as_float(u);
}

__device__ __forceinline__ uint32_t smem_u32(const void* p) {
    uint32_t a;
    asm("{ .reg .u64 t; cvta.to.shared.u64 t, %1; cvt.u32.u64 %0, t; }"
        : "=r"(a) : "l"(p));
    return a;
}

__device__ __forceinline__ void cp_async16(uint32_t dst, const void* src) {
    asm volatile("cp.async.cg.shared.global [%0], [%1], 16;"
                 :: "r"(dst), "l"(src) : "memory");
}

__device__ __forceinline__ void mma_tf32(float& c0, float& c1, float& c2, float& c3,
                                         uint32_t a0, uint32_t a1, uint32_t a2, uint32_t a3,
                                         uint32_t b0, uint32_t b1)
{
    asm volatile(
        "mma.sync.aligned.m16n8k8.row.col.f32.tf32.tf32.f32 "
        "{%0,%1,%2,%3}, {%4,%5,%6,%7}, {%8,%9}, {%0,%1,%2,%3};"
        : "+f"(c0), "+f"(c1), "+f"(c2), "+f"(c3)
        : "r"(a0), "r"(a1), "r"(a2), "r"(a3), "r"(b0), "r"(b1));
}

// ---------------------------------------------------------------------------
__global__ void wtrans_kernel(const float* __restrict__ Wq,
                              const float* __restrict__ Wk,
                              const float* __restrict__ Wv)
{
    int idx = blockIdx.x * blockDim.x + threadIdx.x;
    if (idx >= 3 * NH * CH * DM) return;
    int n = idx & (DM - 1);
    int k = (idx >> 6) & (CH - 1);
    int h = (idx >> 15) & (NH - 1);
    int w = idx >> 18;
    const float* W = (w == 0) ? Wq : (w == 1) ? Wk : Wv;
    float v = W[((size_t)h * CH + k) * DM + n];
    g_wt[(((size_t)(w * NH + h) * DM + n) * CH) + k] = tf32r(v);
}

// ---------------------------------------------------------------------------
__global__ void gather_kernel(const float* __restrict__ x,
                              const float* __restrict__ outbuf,
                              int pass)
{
    int idx = blockIdx.x * blockDim.x + threadIdx.x;
    if (idx >= (NWIN * SEQ * CH) / 4) return;
    int e = idx * 4;
    int c = e & (CH - 1);
    int s = (e >> 9) & (SEQ - 1);
    int n = e >> 17;
    int f  = s >> 6;
    int ry = (s >> 3) & 7;
    int rx = s & 7;
    int b  = n >> 4;
    int by = (n >> 2) & 3;
    int bx = n & 3;
    int gr = by * 8 + ry;
    int gc = bx * 8 + rx;

    const float* src;
    if (pass == 0) {
        src = x + (((((size_t)b * 8 + f) * 32 + gr) * 32 + gc) * CH + c);
    } else if (f < 3) {
        src = outbuf + (((((size_t)b * 8 + (pass + f)) * 32 + gr) * 32 + gc) * CH + c);
    } else {
        src = x + (((((size_t)b * 8 + (pass + 3)) * 32 + gr) * 32 + gc) * CH + c);
    }
    *(float4*)(g_xb + e) = *(const float4*)src;
}

// ---------------------------------------------------------------------------
// QKV GEMM: 128x128 block tile, 8 warps, cp.async double buffer.
// ---------------------------------------------------------------------------
#define AP 36
#define QKV_SMEM (4 * 128 * AP * (int)sizeof(float))   // 2 stages x (A + B)

__global__ __launch_bounds__(256, 2) void qkv_mma_kernel(
    const float* __restrict__ bq, const float* __restrict__ bk,
    const float* __restrict__ bv)
{
    const int m0 = blockIdx.x * 128;
    const int n0 = blockIdx.y * 128;

    extern __shared__ float dyn[];
    float* As[2] = { dyn,              dyn + 128 * AP };
    float* Bs[2] = { dyn + 2*128*AP,   dyn + 3*128*AP };

    const int tid = threadIdx.x;
    const int wid = tid >> 5;
    const int lane = tid & 31;
    const int gid = lane >> 2;
    const int tig = lane & 3;
    const int mwarp = wid & 3;
    const int nwarp = wid >> 2;

    // staging addresses (4 chunks each for A and B per thread)
    uint32_t sA[2][4], sB[2][4];
    const float* gA[4];
    const float* gB[4];
#pragma unroll
    for (int i = 0; i < 4; i++) {
        int chunk = tid + 256 * i;
        int row = chunk >> 3;
        int kg = (chunk & 7) * 4;
        sA[0][i] = smem_u32(As[0] + row * AP + kg);
        sA[1][i] = smem_u32(As[1] + row * AP + kg);
        sB[0][i] = smem_u32(Bs[0] + row * AP + kg);
        sB[1][i] = smem_u32(Bs[1] + row * AP + kg);
        gA[i] = g_xb + (size_t)(m0 + row) * CH + kg;
        gB[i] = g_wt + (size_t)(n0 + row) * CH + kg;
    }

    float c[2][8][4];
#pragma unroll
    for (int mt = 0; mt < 2; mt++)
#pragma unroll
        for (int nt = 0; nt < 8; nt++)
#pragma unroll
            for (int r = 0; r < 4; r++) c[mt][nt][r] = 0.f;

    // prologue: stage k-tile 0
#pragma unroll
    for (int i = 0; i < 4; i++) {
        cp_async16(sA[0][i], gA[i]);
        cp_async16(sB[0][i], gB[i]);
    }
    asm volatile("cp.async.commit_group;" ::: "memory");

    for (int t = 0; t < 16; t++) {
        const int buf = t & 1;
        if (t < 15) {
            const int kc = (t + 1) * 32;
            const int nb = (t + 1) & 1;
#pragma unroll
            for (int i = 0; i < 4; i++) {
                cp_async16(sA[nb][i], gA[i] + kc);
                cp_async16(sB[nb][i], gB[i] + kc);
            }
        }
        asm volatile("cp.async.commit_group;" ::: "memory");
        asm volatile("cp.async.wait_group 1;" ::: "memory");
        __syncthreads();

        const float* Ab = As[buf];
        const float* Bb = Bs[buf];
#pragma unroll
        for (int k8 = 0; k8 < 4; k8++) {
            const int kk = k8 * 8;
            uint32_t af[2][4];
#pragma unroll
            for (int mt = 0; mt < 2; mt++) {
                int rb = mwarp * 32 + mt * 16;
                af[mt][0] = __float_as_uint(Ab[(rb + gid)     * AP + kk + tig]);
                af[mt][1] = __float_as_uint(Ab[(rb + gid + 8) * AP + kk + tig]);
                af[mt][2] = __float_as_uint(Ab[(rb + gid)     * AP + kk + tig + 4]);
                af[mt][3] = __float_as_uint(Ab[(rb + gid + 8) * AP + kk + tig + 4]);
            }
#pragma unroll
            for (int nt = 0; nt < 8; nt++) {
                int nb2 = nwarp * 64 + nt * 8 + gid;
                uint32_t b0 = __float_as_uint(Bb[nb2 * AP + kk + tig]);
                uint32_t b1 = __float_as_uint(Bb[nb2 * AP + kk + tig + 4]);
#pragma unroll
                for (int mt = 0; mt < 2; mt++)
                    mma_tf32(c[mt][nt][0], c[mt][nt][1], c[mt][nt][2], c[mt][nt][3],
                             af[mt][0], af[mt][1], af[mt][2], af[mt][3], b0, b1);
            }
        }
        __syncthreads();
    }

    const int j = blockIdx.y * 2 + nwarp;
    const int wsel = j >> 3;
    const int h = j & 7;
    const float* bias = ((wsel == 0) ? bq : (wsel == 1) ? bk : bv) + h * DM;
    float* outp = (wsel == 0) ? g_q : (wsel == 1) ? g_k : g_v;

#pragma unroll
    for (int mt = 0; mt < 2; mt++) {
#pragma unroll
        for (int half = 0; half < 2; half++) {
            int m = m0 + mwarp * 32 + mt * 16 + gid + half * 8;
            int n = m >> 8;
            int s = m & 255;
            float* rowp = outp + (((size_t)n * NH + h) * SEQ + s) * DM;
#pragma unroll
            for (int nt = 0; nt < 8; nt++) {
                int d = nt * 8 + 2 * tig;
                float2 o;
                o.x = c[mt][nt][half * 2 + 0] + bias[d];
                o.y = c[mt][nt][half * 2 + 1] + bias[d + 1];
                *(float2*)(rowp + d) = o;
            }
        }
    }
}

// ---------------------------------------------------------------------------
// Flash attention per (n, h): 512 threads / 16 warps, 16 query rows each.
// ---------------------------------------------------------------------------
#define KP 68

__global__ __launch_bounds__(512, 1) void attn_tc_kernel(float* __restrict__ outbuf, int pass)
{
    const int n = blockIdx.x >> 3;
    const int h = blockIdx.x & 7;

    extern __shared__ float sm[];
    float* Ks = sm;
    float* Vs = sm + SEQ * KP;
    float* Pq = sm + 2 * SEQ * KP;

    const int tid = threadIdx.x;
    const int wid = tid >> 5;          // 0..15
    const int lane = tid & 31;
    const int gid = lane >> 2;
    const int tig = lane & 3;
    const int wq = wid * 16;           // warp's 16 query rows

    const size_t head_base = ((size_t)n * NH + h) * SEQ * DM;

    for (int i = tid; i < SEQ * (DM / 4); i += 512) {
        int row = i >> 4;
        int cg = (i & 15) * 4;
        float4 k4 = *(const float4*)(g_k + head_base + (size_t)row * DM + cg);
        k4.x = tf32r(k4.x); k4.y = tf32r(k4.y); k4.z = tf32r(k4.z); k4.w = tf32r(k4.w);
        *(float4*)(Ks + row * KP + cg) = k4;
        float4 v4 = *(const float4*)(g_v + head_base + (size_t)row * DM + cg);
        v4.x = tf32r(v4.x); v4.y = tf32r(v4.y); v4.z = tf32r(v4.z); v4.w = tf32r(v4.w);
        *(float4*)(Vs + row * KP + cg) = v4;
        float4 q4 = *(const float4*)(g_q + head_base + (size_t)row * DM + cg);
        q4.x = tf32r(q4.x * 0.125f); q4.y = tf32r(q4.y * 0.125f);
        q4.z = tf32r(q4.z * 0.125f); q4.w = tf32r(q4.w * 0.125f);
        *(float4*)(Pq + row * KP + cg) = q4;
    }
    __syncthreads();

    // Q fragments for one m16 tile
    uint32_t qf[8][4];
#pragma unroll
    for (int kt = 0; kt < 8; kt++) {
        int cc = kt * 8;
        qf[kt][0] = __float_as_uint(Pq[(wq + gid)     * KP + cc + tig]);
        qf[kt][1] = __float_as_uint(Pq[(wq + gid + 8) * KP + cc + tig]);
        qf[kt][2] = __float_as_uint(Pq[(wq + gid)     * KP + cc + tig + 4]);
        qf[kt][3] = __float_as_uint(Pq[(wq + gid + 8) * KP + cc + tig + 4]);
    }
    __syncwarp();

    float o[8][4];
#pragma unroll
    for (int nt = 0; nt < 8; nt++)
#pragma unroll
        for (int r = 0; r < 4; r++) o[nt][r] = 0.f;

    float mrun[2] = { -1e30f, -1e30f };
    float lrun[2] = { 0.f, 0.f };

    for (int kb = 0; kb < 4; kb++) {
        const int kbase = kb * 64;

        float s[8][4];
#pragma unroll
        for (int nt = 0; nt < 8; nt++)
#pragma unroll
            for (int r = 0; r < 4; r++) s[nt][r] = 0.f;

#pragma unroll
        for (int kt = 0; kt < 8; kt++) {
            const int cc = kt * 8;
#pragma unroll
            for (int nt = 0; nt < 8; nt++) {
                int key = kbase + nt * 8 + gid;
                uint32_t b0 = __float_as_uint(Ks[key * KP + cc + tig]);
                uint32_t b1 = __float_as_uint(Ks[key * KP + cc + tig + 4]);
                mma_tf32(s[nt][0], s[nt][1], s[nt][2], s[nt][3],
                         qf[kt][0], qf[kt][1], qf[kt][2], qf[kt][3], b0, b1);
            }
        }

        // online softmax (2 row-slots: gid, gid+8)
        float mloc[2] = { -1e30f, -1e30f };
#pragma unroll
        for (int nt = 0; nt < 8; nt++) {
            mloc[0] = fmaxf(mloc[0], fmaxf(s[nt][0], s[nt][1]));
            mloc[1] = fmaxf(mloc[1], fmaxf(s[nt][2], s[nt][3]));
        }
#pragma unroll
        for (int z = 0; z < 2; z++) {
            mloc[z] = fmaxf(mloc[z], __shfl_xor_sync(0xffffffffu, mloc[z], 1));
            mloc[z] = fmaxf(mloc[z], __shfl_xor_sync(0xffffffffu, mloc[z], 2));
        }
        float scale[2], lsum[2];
#pragma unroll
        for (int z = 0; z < 2; z++) {
            float mnew = fmaxf(mrun[z], mloc[z]);
            scale[z] = __expf(mrun[z] - mnew);
            mrun[z] = mnew;
            lsum[z] = 0.f;
        }
#pragma unroll
        for (int nt = 0; nt < 8; nt++) {
            s[nt][0] = __expf(s[nt][0] - mrun[0]);
            s[nt][1] = __expf(s[nt][1] - mrun[0]);
            s[nt][2] = __expf(s[nt][2] - mrun[1]);
            s[nt][3] = __expf(s[nt][3] - mrun[1]);
            lsum[0] += s[nt][0] + s[nt][1];
            lsum[1] += s[nt][2] + s[nt][3];
        }
#pragma unroll
        for (int z = 0; z < 2; z++) {
            lsum[z] += __shfl_xor_sync(0xffffffffu, lsum[z], 1);
            lsum[z] += __shfl_xor_sync(0xffffffffu, lsum[z], 2);
            lrun[z] = lrun[z] * scale[z] + lsum[z];
        }
#pragma unroll
        for (int nt = 0; nt < 8; nt++) {
            o[nt][0] *= scale[0];
            o[nt][1] *= scale[0];
            o[nt][2] *= scale[1];
            o[nt][3] *= scale[1];
        }

        // P -> warp-private slab (rows wq..wq+15), reload as a-layout into s
        __syncwarp();
#pragma unroll
        for (int nt = 0; nt < 8; nt++) {
            int col = nt * 8 + 2 * tig;
            float2 p0, p1;
            p0.x = tf32r(s[nt][0]); p0.y = tf32r(s[nt][1]);
            p1.x = tf32r(s[nt][2]); p1.y = tf32r(s[nt][3]);
            *(float2*)(Pq + (wq + gid)     * KP + col) = p0;
            *(float2*)(Pq + (wq + gid + 8) * KP + col) = p1;
        }
        __syncwarp();
#pragma unroll
        for (int kt = 0; kt < 8; kt++) {
            int cc = kt * 8;
            s[kt][0] = Pq[(wq + gid)     * KP + cc + tig];
            s[kt][1] = Pq[(wq + gid + 8) * KP + cc + tig];
            s[kt][2] = Pq[(wq + gid)     * KP + cc + tig + 4];
            s[kt][3] = Pq[(wq + gid + 8) * KP + cc + tig + 4];
        }
        __syncwarp();

        // O += P * V
#pragma unroll
        for (int kt = 0; kt < 8; kt++) {
#pragma unroll
            for (int nt = 0; nt < 8; nt++) {
                int dmc = nt * 8 + gid;
                uint32_t b0 = __float_as_uint(Vs[(kbase + kt * 8 + tig)     * KP + dmc]);
                uint32_t b1 = __float_as_uint(Vs[(kbase + kt * 8 + tig + 4) * KP + dmc]);
                mma_tf32(o[nt][0], o[nt][1], o[nt][2], o[nt][3],
                         __float_as_uint(s[kt][0]), __float_as_uint(s[kt][1]),
                         __float_as_uint(s[kt][2]), __float_as_uint(s[kt][3]),
                         b0, b1);
            }
        }
    }

    float inv[2] = { 1.f / lrun[0], 1.f / lrun[1] };

    const int b  = n >> 4;
    const int by = (n >> 2) & 3;
    const int bx = n & 3;

#pragma unroll
    for (int hh = 0; hh < 2; hh++) {
        int q = wq + gid + 8 * hh;
        int f  = q >> 6;
        int ry = (q >> 3) & 7;
        int rx = q & 7;
        int gr = by * 8 + ry;
        int gc = bx * 8 + rx;
        int frame = pass + f;
        float* dst = outbuf + (((((size_t)b * 8 + frame) * 32 + gr) * 32 + gc) * CH) + h * DM;
        const float* res = g_xb + ((size_t)n * SEQ + q) * CH + h * DM;
        float sc = inv[hh];
#pragma unroll
        for (int nt = 0; nt < 8; nt++) {
            int d = nt * 8 + 2 * tig;
            float2 r = *(const float2*)(res + d);
            float2 ov;
            ov.x = o[nt][2 * hh + 0] * sc + r.x;
            ov.y = o[nt][2 * hh + 1] * sc + r.y;
            *(float2*)(dst + d) = ov;
        }
    }
}

// ---------------------------------------------------------------------------
extern "C" void kernel_launch(void* const* d_in, const int* in_sizes, int n_in,
                              void* d_out, int out_size)
{
    const float* x  = (const float*)d_in[0];
    const float* Wq = (const float*)d_in[1];
    const float* Wk = (const float*)d_in[2];
    const float* Wv = (const float*)d_in[3];
    const float* bq = (const float*)d_in[4];
    const float* bk = (const float*)d_in[5];
    const float* bv = (const float*)d_in[6];
    float* out = (float*)d_out;

    const int attn_smem = 3 * SEQ * KP * (int)sizeof(float);
    cudaFuncSetAttribute(attn_tc_kernel, cudaFuncAttributeMaxDynamicSharedMemorySize,
                         attn_smem);
    cudaFuncSetAttribute(qkv_mma_kernel, cudaFuncAttributeMaxDynamicSharedMemorySize,
                         QKV_SMEM);

    wtrans_kernel<<<(3 * NH * CH * DM + 255) / 256, 256>>>(Wq, Wk, Wv);

    const int gather_blocks = (NWIN * SEQ * CH / 4 + 255) / 256;

    for (int pass = 0; pass <= 4; pass++) {
        gather_kernel<<<gather_blocks, 256>>>(x, out, pass);
        dim3 gq((NWIN * SEQ) / 128, NTOT / 128);
        qkv_mma_kernel<<<gq, 256, QKV_SMEM>>>(bq, bk, bv);
        attn_tc_kernel<<<NWIN * NH, 512, attn_smem>>>(out, pass);
    }
}

// round 6
// speedup vs baseline: 3.4334x; 1.1451x over previous
#include <cuda_runtime.h>
#include <math.h>
#include <stdint.h>

// ---------------------------------------------------------------------------
// SpaceTimeLocalSelfAttention — R6: fully fused QKV + flash attention
//   One block per (window n, head h). QKV GEMM -> smem -> attention -> out.
// B=4, T=8, H=W=32, C=512, NH=8, DM=64, KT=4, KS=8
// ---------------------------------------------------------------------------

#define NWIN   64
#define SEQ    256
#define CH     512
#define NH     8
#define DM     64
#define JC     192        // fused q|k|v columns per head
#define KP     68         // K/V/Pq smem pitch
#define SP     20         // GEMM staging pitch (conflict-free for frag reads)

__device__ float g_xb[NWIN * SEQ * CH];
__device__ float g_wt[NH * JC * CH];   // [h][j][k], j = w*64+dm, tf32-rounded

__device__ __forceinline__ float tf32r(float x) {
    uint32_t u;
    asm("cvt.rna.tf32.f32 %0, %1;" : "=r"(u) : "f"(x));
    return __uint_as_float(u);
}

__device__ __forceinline__ uint32_t smem_u32(const void* p) {
    uint32_t a;
    asm("{ .reg .u64 t; cvta.to.shared.u64 t, %1; cvt.u32.u64 %0, t; }"
        : "=r"(a) : "l"(p));
    return a;
}

__device__ __forceinline__ void cp_async16(uint32_t dst, const void* src) {
    asm volatile("cp.async.cg.shared.global [%0], [%1], 16;"
                 :: "r"(dst), "l"(src) : "memory");
}

__device__ __forceinline__ void mma_tf32(float& c0, float& c1, float& c2, float& c3,
                                         uint32_t a0, uint32_t a1, uint32_t a2, uint32_t a3,
                                         uint32_t b0, uint32_t b1)
{
    asm volatile(
        "mma.sync.aligned.m16n8k8.row.col.f32.tf32.tf32.f32 "
        "{%0,%1,%2,%3}, {%4,%5,%6,%7}, {%8,%9}, {%0,%1,%2,%3};"
        : "+f"(c0), "+f"(c1), "+f"(c2), "+f"(c3)
        : "r"(a0), "r"(a1), "r"(a2), "r"(a3), "r"(b0), "r"(b1));
}

// ---------------------------------------------------------------------------
__global__ void wtrans_kernel(const float* __restrict__ Wq,
                              const float* __restrict__ Wk,
                              const float* __restrict__ Wv)
{
    int idx = blockIdx.x * blockDim.x + threadIdx.x;
    if (idx >= 3 * NH * CH * DM) return;
    int dm = idx & (DM - 1);
    int k  = (idx >> 6) & (CH - 1);
    int h  = (idx >> 15) & (NH - 1);
    int w  = idx >> 18;
    const float* W = (w == 0) ? Wq : (w == 1) ? Wk : Wv;
    float v = W[((size_t)h * CH + k) * DM + dm];
    int j = w * DM + dm;
    g_wt[((size_t)h * JC + j) * CH + k] = tf32r(v);
}

// ---------------------------------------------------------------------------
__global__ void gather_kernel(const float* __restrict__ x,
                              const float* __restrict__ outbuf,
                              int pass)
{
    int idx = blockIdx.x * blockDim.x + threadIdx.x;
    if (idx >= (NWIN * SEQ * CH) / 4) return;
    int e = idx * 4;
    int c = e & (CH - 1);
    int s = (e >> 9) & (SEQ - 1);
    int n = e >> 17;
    int f  = s >> 6;
    int ry = (s >> 3) & 7;
    int rx = s & 7;
    int b  = n >> 4;
    int by = (n >> 2) & 3;
    int bx = n & 3;
    int gr = by * 8 + ry;
    int gc = bx * 8 + rx;

    const float* src;
    if (pass == 0) {
        src = x + (((((size_t)b * 8 + f) * 32 + gr) * 32 + gc) * CH + c);
    } else if (f < 3) {
        src = outbuf + (((((size_t)b * 8 + (pass + f)) * 32 + gr) * 32 + gc) * CH + c);
    } else {
        src = x + (((((size_t)b * 8 + (pass + 3)) * 32 + gr) * 32 + gc) * CH + c);
    }
    *(float4*)(g_xb + e) = *(const float4*)src;
}

// ---------------------------------------------------------------------------
// Fused kernel: block = (n, h), 256 threads / 8 warps.
//   Phase 1: QKV GEMM [256x512]x[512x192], cp.async double buffered.
//   Phase 2: write Q(scaled)/K/V to smem slabs (bias added, tf32).
//   Phase 3: flash attention (tf32 mma), residual, scatter to out.
// ---------------------------------------------------------------------------
#define FUSED_SMEM (3 * SEQ * KP * (int)sizeof(float))

__global__ __launch_bounds__(256, 1) void fused_kernel(
    float* __restrict__ outbuf, int pass,
    const float* __restrict__ bq, const float* __restrict__ bk,
    const float* __restrict__ bv)
{
    const int n = blockIdx.x >> 3;
    const int h = blockIdx.x & 7;

    extern __shared__ float sm[];
    float* Ks = sm;
    float* Vs = sm + SEQ * KP;
    float* Pq = sm + 2 * SEQ * KP;
    // GEMM staging slabs live inside Pq (A) and Vs (B) — unused until phase 2.
    float* Asl[2] = { Pq, Pq + SEQ * SP };
    float* Bsl[2] = { Vs, Vs + JC * SP };

    __shared__ float bias_sm[JC];

    const int tid = threadIdx.x;
    const int wid = tid >> 5;          // 0..7
    const int lane = tid & 31;
    const int gid = lane >> 2;
    const int tig = lane & 3;
    const int wq = wid * 32;           // warp's 32 rows

    if (tid < JC) {
        int dm = tid & 63;
        int wsel = tid >> 6;
        const float* bb = (wsel == 0) ? bq : (wsel == 1) ? bk : bv;
        bias_sm[tid] = bb[h * DM + dm];
    }

    const float* Abase = g_xb + (size_t)n * SEQ * CH;
    const float* Bbase = g_wt + (size_t)h * JC * CH;

    float c[2][24][4];
#pragma unroll
    for (int mt = 0; mt < 2; mt++)
#pragma unroll
        for (int nt = 0; nt < 24; nt++)
#pragma unroll
            for (int r = 0; r < 4; r++) c[mt][nt][r] = 0.f;

    // ---- Phase 1: GEMM over 32 k-chunks of 16 ----
    // prologue: stage chunk 0 into buffer 0
    {
#pragma unroll
        for (int i = 0; i < 4; i++) {
            int chunk = tid + 256 * i;
            int row = chunk >> 2;
            int cg = (chunk & 3) * 4;
            cp_async16(smem_u32(Asl[0] + row * SP + cg), Abase + (size_t)row * CH + cg);
        }
#pragma unroll
        for (int i = 0; i < 3; i++) {
            int chunk = tid + 256 * i;
            int row = chunk >> 2;
            int cg = (chunk & 3) * 4;
            cp_async16(smem_u32(Bsl[0] + row * SP + cg), Bbase + (size_t)row * CH + cg);
        }
        asm volatile("cp.async.commit_group;" ::: "memory");
    }

    for (int t = 0; t < 32; t++) {
        const int buf = t & 1;
        if (t < 31) {
            const int kc = (t + 1) * 16;
            const int nb = (t + 1) & 1;
#pragma unroll
            for (int i = 0; i < 4; i++) {
                int chunk = tid + 256 * i;
                int row = chunk >> 2;
                int cg = (chunk & 3) * 4;
                cp_async16(smem_u32(Asl[nb] + row * SP + cg),
                           Abase + (size_t)row * CH + kc + cg);
            }
#pragma unroll
            for (int i = 0; i < 3; i++) {
                int chunk = tid + 256 * i;
                int row = chunk >> 2;
                int cg = (chunk & 3) * 4;
                cp_async16(smem_u32(Bsl[nb] + row * SP + cg),
                           Bbase + (size_t)row * CH + kc + cg);
            }
        }
        asm volatile("cp.async.commit_group;" ::: "memory");
        asm volatile("cp.async.wait_group 1;" ::: "memory");
        __syncthreads();

        const float* Ab = Asl[buf];
        const float* Bb = Bsl[buf];
#pragma unroll
        for (int k8 = 0; k8 < 2; k8++) {
            const int kk = k8 * 8;
            uint32_t af[2][4];
#pragma unroll
            for (int mt = 0; mt < 2; mt++) {
                int rb = wq + mt * 16;
                af[mt][0] = __float_as_uint(Ab[(rb + gid)     * SP + kk + tig]);
                af[mt][1] = __float_as_uint(Ab[(rb + gid + 8) * SP + kk + tig]);
                af[mt][2] = __float_as_uint(Ab[(rb + gid)     * SP + kk + tig + 4]);
                af[mt][3] = __float_as_uint(Ab[(rb + gid + 8) * SP + kk + tig + 4]);
            }
#pragma unroll
            for (int nt = 0; nt < 24; nt++) {
                uint32_t b0 = __float_as_uint(Bb[(nt * 8 + gid) * SP + kk + tig]);
                uint32_t b1 = __float_as_uint(Bb[(nt * 8 + gid) * SP + kk + tig + 4]);
#pragma unroll
                for (int mt = 0; mt < 2; mt++)
                    mma_tf32(c[mt][nt][0], c[mt][nt][1], c[mt][nt][2], c[mt][nt][3],
                             af[mt][0], af[mt][1], af[mt][2], af[mt][3], b0, b1);
            }
        }
        __syncthreads();
    }

    // ---- Phase 2: write Q (x0.125) / K / V into smem slabs ----
#pragma unroll
    for (int mt = 0; mt < 2; mt++) {
        int r0 = wq + mt * 16 + gid;
        int r1 = r0 + 8;
#pragma unroll
        for (int nt = 0; nt < 24; nt++) {
            int col = nt * 8 + 2 * tig;
            float b0 = bias_sm[col], b1 = bias_sm[col + 1];
            float v00 = c[mt][nt][0] + b0, v01 = c[mt][nt][1] + b1;
            float v10 = c[mt][nt][2] + b0, v11 = c[mt][nt][3] + b1;
            if (nt < 8) {
                float2 p0, p1;
                p0.x = tf32r(v00 * 0.125f); p0.y = tf32r(v01 * 0.125f);
                p1.x = tf32r(v10 * 0.125f); p1.y = tf32r(v11 * 0.125f);
                *(float2*)(Pq + r0 * KP + col) = p0;
                *(float2*)(Pq + r1 * KP + col) = p1;
            } else if (nt < 16) {
                int d = col - 64;
                float2 p0, p1;
                p0.x = tf32r(v00); p0.y = tf32r(v01);
                p1.x = tf32r(v10); p1.y = tf32r(v11);
                *(float2*)(Ks + r0 * KP + d) = p0;
                *(float2*)(Ks + r1 * KP + d) = p1;
            } else {
                int d = col - 128;
                float2 p0, p1;
                p0.x = tf32r(v00); p0.y = tf32r(v01);
                p1.x = tf32r(v10); p1.y = tf32r(v11);
                *(float2*)(Vs + r0 * KP + d) = p0;
                *(float2*)(Vs + r1 * KP + d) = p1;
            }
        }
    }
    __syncthreads();

    // ---- Phase 3: flash attention (R4 structure) ----
    uint32_t qf[2][8][4];
#pragma unroll
    for (int mt = 0; mt < 2; mt++) {
        int rb = wq + mt * 16;
#pragma unroll
        for (int kt = 0; kt < 8; kt++) {
            int cc = kt * 8;
            qf[mt][kt][0] = __float_as_uint(Pq[(rb + gid)     * KP + cc + tig]);
            qf[mt][kt][1] = __float_as_uint(Pq[(rb + gid + 8) * KP + cc + tig]);
            qf[mt][kt][2] = __float_as_uint(Pq[(rb + gid)     * KP + cc + tig + 4]);
            qf[mt][kt][3] = __float_as_uint(Pq[(rb + gid + 8) * KP + cc + tig + 4]);
        }
    }
    __syncwarp();

    float o[2][8][4];
#pragma unroll
    for (int mt = 0; mt < 2; mt++)
#pragma unroll
        for (int nt = 0; nt < 8; nt++)
#pragma unroll
            for (int r = 0; r < 4; r++) o[mt][nt][r] = 0.f;

    float mrun[4], lrun[4];
#pragma unroll
    for (int z = 0; z < 4; z++) { mrun[z] = -1e30f; lrun[z] = 0.f; }

    for (int kb = 0; kb < 4; kb++) {
        const int kbase = kb * 64;

        float s[2][8][4];
#pragma unroll
        for (int mt = 0; mt < 2; mt++)
#pragma unroll
            for (int nt = 0; nt < 8; nt++)
#pragma unroll
                for (int r = 0; r < 4; r++) s[mt][nt][r] = 0.f;

#pragma unroll
        for (int kt = 0; kt < 8; kt++) {
            const int cc = kt * 8;
#pragma unroll
            for (int nt = 0; nt < 8; nt++) {
                int key = kbase + nt * 8 + gid;
                uint32_t b0 = __float_as_uint(Ks[key * KP + cc + tig]);
                uint32_t b1 = __float_as_uint(Ks[key * KP + cc + tig + 4]);
#pragma unroll
                for (int mt = 0; mt < 2; mt++)
                    mma_tf32(s[mt][nt][0], s[mt][nt][1], s[mt][nt][2], s[mt][nt][3],
                             qf[mt][kt][0], qf[mt][kt][1], qf[mt][kt][2], qf[mt][kt][3],
                             b0, b1);
            }
        }

        float mloc[4];
#pragma unroll
        for (int z = 0; z < 4; z++) mloc[z] = -1e30f;
#pragma unroll
        for (int mt = 0; mt < 2; mt++)
#pragma unroll
            for (int nt = 0; nt < 8; nt++) {
                mloc[mt * 2 + 0] = fmaxf(mloc[mt * 2 + 0], fmaxf(s[mt][nt][0], s[mt][nt][1]));
                mloc[mt * 2 + 1] = fmaxf(mloc[mt * 2 + 1], fmaxf(s[mt][nt][2], s[mt][nt][3]));
            }
#pragma unroll
        for (int z = 0; z < 4; z++) {
            mloc[z] = fmaxf(mloc[z], __shfl_xor_sync(0xffffffffu, mloc[z], 1));
            mloc[z] = fmaxf(mloc[z], __shfl_xor_sync(0xffffffffu, mloc[z], 2));
        }
        float scale[4], lsum[4];
#pragma unroll
        for (int z = 0; z < 4; z++) {
            float mnew = fmaxf(mrun[z], mloc[z]);
            scale[z] = __expf(mrun[z] - mnew);
            mrun[z] = mnew;
            lsum[z] = 0.f;
        }
#pragma unroll
        for (int mt = 0; mt < 2; mt++)
#pragma unroll
            for (int nt = 0; nt < 8; nt++) {
                s[mt][nt][0] = __expf(s[mt][nt][0] - mrun[mt * 2 + 0]);
                s[mt][nt][1] = __expf(s[mt][nt][1] - mrun[mt * 2 + 0]);
                s[mt][nt][2] = __expf(s[mt][nt][2] - mrun[mt * 2 + 1]);
                s[mt][nt][3] = __expf(s[mt][nt][3] - mrun[mt * 2 + 1]);
                lsum[mt * 2 + 0] += s[mt][nt][0] + s[mt][nt][1];
                lsum[mt * 2 + 1] += s[mt][nt][2] + s[mt][nt][3];
            }
#pragma unroll
        for (int z = 0; z < 4; z++) {
            lsum[z] += __shfl_xor_sync(0xffffffffu, lsum[z], 1);
            lsum[z] += __shfl_xor_sync(0xffffffffu, lsum[z], 2);
            lrun[z] = lrun[z] * scale[z] + lsum[z];
        }
#pragma unroll
        for (int mt = 0; mt < 2; mt++)
#pragma unroll
            for (int nt = 0; nt < 8; nt++) {
                o[mt][nt][0] *= scale[mt * 2 + 0];
                o[mt][nt][1] *= scale[mt * 2 + 0];
                o[mt][nt][2] *= scale[mt * 2 + 1];
                o[mt][nt][3] *= scale[mt * 2 + 1];
            }

        // P -> warp-private rows of Pq (overwrites this warp's Q; qf is in regs)
        __syncwarp();
#pragma unroll
        for (int mt = 0; mt < 2; mt++) {
            int rb = wq + mt * 16;
#pragma unroll
            for (int nt = 0; nt < 8; nt++) {
                int col = nt * 8 + 2 * tig;
                float2 p0, p1;
                p0.x = tf32r(s[mt][nt][0]); p0.y = tf32r(s[mt][nt][1]);
                p1.x = tf32r(s[mt][nt][2]); p1.y = tf32r(s[mt][nt][3]);
                *(float2*)(Pq + (rb + gid)     * KP + col) = p0;
                *(float2*)(Pq + (rb + gid + 8) * KP + col) = p1;
            }
        }
        __syncwarp();
#pragma unroll
        for (int mt = 0; mt < 2; mt++) {
            int rb = wq + mt * 16;
#pragma unroll
            for (int kt = 0; kt < 8; kt++) {
                int cc = kt * 8;
                s[mt][kt][0] = Pq[(rb + gid)     * KP + cc + tig];
                s[mt][kt][1] = Pq[(rb + gid + 8) * KP + cc + tig];
                s[mt][kt][2] = Pq[(rb + gid)     * KP + cc + tig + 4];
                s[mt][kt][3] = Pq[(rb + gid + 8) * KP + cc + tig + 4];
            }
        }
        __syncwarp();

#pragma unroll
        for (int kt = 0; kt < 8; kt++) {
#pragma unroll
            for (int nt = 0; nt < 8; nt++) {
                int dmc = nt * 8 + gid;
                uint32_t b0 = __float_as_uint(Vs[(kbase + kt * 8 + tig)     * KP + dmc]);
                uint32_t b1 = __float_as_uint(Vs[(kbase + kt * 8 + tig + 4) * KP + dmc]);
#pragma unroll
                for (int mt = 0; mt < 2; mt++)
                    mma_tf32(o[mt][nt][0], o[mt][nt][1], o[mt][nt][2], o[mt][nt][3],
                             __float_as_uint(s[mt][kt][0]), __float_as_uint(s[mt][kt][1]),
                             __float_as_uint(s[mt][kt][2]), __float_as_uint(s[mt][kt][3]),
                             b0, b1);
            }
        }
    }

    // ---- epilogue: normalize, residual, scatter ----
    float inv[4];
#pragma unroll
    for (int z = 0; z < 4; z++) inv[z] = 1.f / lrun[z];

    const int b  = n >> 4;
    const int by = (n >> 2) & 3;
    const int bx = n & 3;

#pragma unroll
    for (int mt = 0; mt < 2; mt++) {
#pragma unroll
        for (int hh = 0; hh < 2; hh++) {
            int q = wq + mt * 16 + gid + 8 * hh;
            int f  = q >> 6;
            int ry = (q >> 3) & 7;
            int rx = q & 7;
            int gr = by * 8 + ry;
            int gc = bx * 8 + rx;
            int frame = pass + f;
            float* dst = outbuf + (((((size_t)b * 8 + frame) * 32 + gr) * 32 + gc) * CH) + h * DM;
            const float* res = g_xb + ((size_t)n * SEQ + q) * CH + h * DM;
            float sc = inv[mt * 2 + hh];
#pragma unroll
            for (int nt = 0; nt < 8; nt++) {
                int d = nt * 8 + 2 * tig;
                float2 r = *(const float2*)(res + d);
                float2 ov;
                ov.x = o[mt][nt][2 * hh + 0] * sc + r.x;
                ov.y = o[mt][nt][2 * hh + 1] * sc + r.y;
                *(float2*)(dst + d) = ov;
            }
        }
    }
}

// ---------------------------------------------------------------------------
extern "C" void kernel_launch(void* const* d_in, const int* in_sizes, int n_in,
                              void* d_out, int out_size)
{
    const float* x  = (const float*)d_in[0];
    const float* Wq = (const float*)d_in[1];
    const float* Wk = (const float*)d_in[2];
    const float* Wv = (const float*)d_in[3];
    const float* bq = (const float*)d_in[4];
    const float* bk = (const float*)d_in[5];
    const float* bv = (const float*)d_in[6];
    float* out = (float*)d_out;

    cudaFuncSetAttribute(fused_kernel, cudaFuncAttributeMaxDynamicSharedMemorySize,
                         FUSED_SMEM);

    wtrans_kernel<<<(3 * NH * CH * DM + 255) / 256, 256>>>(Wq, Wk, Wv);

    const int gather_blocks = (NWIN * SEQ * CH / 4 + 255) / 256;

    for (int pass = 0; pass <= 4; pass++) {
        gather_kernel<<<gather_blocks, 256>>>(x, out, pass);
        fused_kernel<<<NWIN * NH, 256, FUSED_SMEM>>>(out, pass, bq, bk, bv);
    }
}

// round 7
// speedup vs baseline: 3.5576x; 1.0362x over previous
#include <cuda_runtime.h>
#include <math.h>
#include <stdint.h>

// ---------------------------------------------------------------------------
// SpaceTimeLocalSelfAttention — R7: fused kernel with conflict-free smem
//   B staged k-major (pitch 200), K transposed (pitch 264), V pitch 72.
// B=4, T=8, H=W=32, C=512, NH=8, DM=64, KT=4, KS=8
// ---------------------------------------------------------------------------

#define NWIN   64
#define SEQ    256
#define CH     512
#define NH     8
#define DM     64
#define JC     192        // fused q|k|v columns per head
#define KP     68         // Pq pitch (Q/P slab)
#define KTP    264        // Kt pitch (transposed K: [d][key])
#define VP     72         // V pitch ([key][d])
#define SP     20         // A staging pitch
#define BP     200        // B staging pitch (k-major: [k][j])

__device__ float g_xb[NWIN * SEQ * CH];
__device__ float g_wt[NH * CH * JC];   // [h][k][j], tf32-rounded

__device__ __forceinline__ float tf32r(float x) {
    uint32_t u;
    asm("cvt.rna.tf32.f32 %0, %1;" : "=r"(u) : "f"(x));
    return __uint_as_float(u);
}

__device__ __forceinline__ uint32_t smem_u32(const void* p) {
    uint32_t a;
    asm("{ .reg .u64 t; cvta.to.shared.u64 t, %1; cvt.u32.u64 %0, t; }"
        : "=r"(a) : "l"(p));
    return a;
}

__device__ __forceinline__ void cp_async16(uint32_t dst, const void* src) {
    asm volatile("cp.async.cg.shared.global [%0], [%1], 16;"
                 :: "r"(dst), "l"(src) : "memory");
}

__device__ __forceinline__ void mma_tf32(float& c0, float& c1, float& c2, float& c3,
                                         uint32_t a0, uint32_t a1, uint32_t a2, uint32_t a3,
                                         uint32_t b0, uint32_t b1)
{
    asm volatile(
        "mma.sync.aligned.m16n8k8.row.col.f32.tf32.tf32.f32 "
        "{%0,%1,%2,%3}, {%4,%5,%6,%7}, {%8,%9}, {%0,%1,%2,%3};"
        : "+f"(c0), "+f"(c1), "+f"(c2), "+f"(c3)
        : "r"(a0), "r"(a1), "r"(a2), "r"(a3), "r"(b0), "r"(b1));
}

// ---------------------------------------------------------------------------
__global__ void wtrans_kernel(const float* __restrict__ Wq,
                              const float* __restrict__ Wk,
                              const float* __restrict__ Wv)
{
    int idx = blockIdx.x * blockDim.x + threadIdx.x;
    if (idx >= 3 * NH * CH * DM) return;
    int dm = idx & (DM - 1);
    int k  = (idx >> 6) & (CH - 1);
    int h  = (idx >> 15) & (NH - 1);
    int w  = idx >> 18;
    const float* W = (w == 0) ? Wq : (w == 1) ? Wk : Wv;
    float v = W[((size_t)h * CH + k) * DM + dm];
    g_wt[((size_t)h * CH + k) * JC + w * DM + dm] = tf32r(v);
}

// ---------------------------------------------------------------------------
__global__ void gather_kernel(const float* __restrict__ x,
                              const float* __restrict__ outbuf,
                              int pass)
{
    int idx = blockIdx.x * blockDim.x + threadIdx.x;
    if (idx >= (NWIN * SEQ * CH) / 4) return;
    int e = idx * 4;
    int c = e & (CH - 1);
    int s = (e >> 9) & (SEQ - 1);
    int n = e >> 17;
    int f  = s >> 6;
    int ry = (s >> 3) & 7;
    int rx = s & 7;
    int b  = n >> 4;
    int by = (n >> 2) & 3;
    int bx = n & 3;
    int gr = by * 8 + ry;
    int gc = bx * 8 + rx;

    const float* src;
    if (pass == 0) {
        src = x + (((((size_t)b * 8 + f) * 32 + gr) * 32 + gc) * CH + c);
    } else if (f < 3) {
        src = outbuf + (((((size_t)b * 8 + (pass + f)) * 32 + gr) * 32 + gc) * CH + c);
    } else {
        src = x + (((((size_t)b * 8 + (pass + 3)) * 32 + gr) * 32 + gc) * CH + c);
    }
    *(float4*)(g_xb + e) = *(const float4*)src;
}

// ---------------------------------------------------------------------------
// Fused: block = (n, h), 256 threads / 8 warps.
// smem (floats): Pq[256*68] | Kt[64*264] | Vs[256*72]  = 206 KB
// ---------------------------------------------------------------------------
#define PQ_FLOATS (SEQ * KP)          // 17408
#define KT_FLOATS (DM * KTP)          // 16896
#define VS_FLOATS (SEQ * VP)          // 18432
#define FUSED_SMEM ((PQ_FLOATS + KT_FLOATS + VS_FLOATS) * (int)sizeof(float))

__global__ __launch_bounds__(256, 1) void fused_kernel(
    float* __restrict__ outbuf, int pass,
    const float* __restrict__ bq, const float* __restrict__ bk,
    const float* __restrict__ bv)
{
    const int n = blockIdx.x >> 3;
    const int h = blockIdx.x & 7;

    extern __shared__ float sm[];
    float* Pq = sm;
    float* Kt = sm + PQ_FLOATS;
    float* Vs = sm + PQ_FLOATS + KT_FLOATS;
    // GEMM staging overlays: A in Pq region, B in Vs region (dead until phase 2)
    float* Asl[2] = { Pq, Pq + SEQ * SP };
    float* Bsl[2] = { Vs, Vs + 16 * BP };

    __shared__ float bias_sm[JC];

    const int tid = threadIdx.x;
    const int wid = tid >> 5;          // 0..7
    const int lane = tid & 31;
    const int gid = lane >> 2;
    const int tig = lane & 3;
    const int wq = wid * 32;

    if (tid < JC) {
        int dm = tid & 63;
        int wsel = tid >> 6;
        const float* bb = (wsel == 0) ? bq : (wsel == 1) ? bk : bv;
        bias_sm[tid] = bb[h * DM + dm];
    }

    const float* Abase = g_xb + (size_t)n * SEQ * CH;
    const float* Bbase = g_wt + (size_t)h * CH * JC;

    float c[2][24][4];
#pragma unroll
    for (int mt = 0; mt < 2; mt++)
#pragma unroll
        for (int nt = 0; nt < 24; nt++)
#pragma unroll
            for (int r = 0; r < 4; r++) c[mt][nt][r] = 0.f;

    // ---- Phase 1: GEMM, 32 k-chunks of 16, double buffered ----
    {
#pragma unroll
        for (int i = 0; i < 4; i++) {               // A: 256 rows x 4 chunks
            int chunk = tid + 256 * i;
            int row = chunk >> 2;
            int cg = (chunk & 3) * 4;
            cp_async16(smem_u32(Asl[0] + row * SP + cg), Abase + (size_t)row * CH + cg);
        }
#pragma unroll
        for (int i = 0; i < 3; i++) {               // B: 16 k-rows x 48 chunks
            int chunk = tid + 256 * i;
            int krow = chunk / 48;
            int cg = (chunk % 48) * 4;
            cp_async16(smem_u32(Bsl[0] + krow * BP + cg), Bbase + (size_t)krow * JC + cg);
        }
        asm volatile("cp.async.commit_group;" ::: "memory");
    }

    for (int t = 0; t < 32; t++) {
        const int buf = t & 1;
        if (t < 31) {
            const int kc = (t + 1) * 16;
            const int nb = (t + 1) & 1;
#pragma unroll
            for (int i = 0; i < 4; i++) {
                int chunk = tid + 256 * i;
                int row = chunk >> 2;
                int cg = (chunk & 3) * 4;
                cp_async16(smem_u32(Asl[nb] + row * SP + cg),
                           Abase + (size_t)row * CH + kc + cg);
            }
#pragma unroll
            for (int i = 0; i < 3; i++) {
                int chunk = tid + 256 * i;
                int krow = chunk / 48;
                int cg = (chunk % 48) * 4;
                cp_async16(smem_u32(Bsl[nb] + krow * BP + cg),
                           Bbase + (size_t)(kc + krow) * JC + cg);
            }
        }
        asm volatile("cp.async.commit_group;" ::: "memory");
        asm volatile("cp.async.wait_group 1;" ::: "memory");
        __syncthreads();

        const float* Ab = Asl[buf];
        const float* Bb = Bsl[buf];
#pragma unroll
        for (int k8 = 0; k8 < 2; k8++) {
            const int kk = k8 * 8;
            uint32_t af[2][4];
#pragma unroll
            for (int mt = 0; mt < 2; mt++) {
                int rb = wq + mt * 16;
                af[mt][0] = __float_as_uint(Ab[(rb + gid)     * SP + kk + tig]);
                af[mt][1] = __float_as_uint(Ab[(rb + gid + 8) * SP + kk + tig]);
                af[mt][2] = __float_as_uint(Ab[(rb + gid)     * SP + kk + tig + 4]);
                af[mt][3] = __float_as_uint(Ab[(rb + gid + 8) * SP + kk + tig + 4]);
            }
#pragma unroll
            for (int nt = 0; nt < 24; nt++) {
                int j = nt * 8 + gid;
                uint32_t b0 = __float_as_uint(Bb[(kk + tig)     * BP + j]);
                uint32_t b1 = __float_as_uint(Bb[(kk + tig + 4) * BP + j]);
#pragma unroll
                for (int mt = 0; mt < 2; mt++)
                    mma_tf32(c[mt][nt][0], c[mt][nt][1], c[mt][nt][2], c[mt][nt][3],
                             af[mt][0], af[mt][1], af[mt][2], af[mt][3], b0, b1);
            }
        }
        __syncthreads();
    }

    // ---- Phase 2: write Q(x0.125)->Pq, K->Kt (transposed), V->Vs ----
#pragma unroll
    for (int mt = 0; mt < 2; mt++) {
        int r0 = wq + mt * 16 + gid;
        int r1 = r0 + 8;
#pragma unroll
        for (int nt = 0; nt < 24; nt++) {
            int col = nt * 8 + 2 * tig;
            float b0 = bias_sm[col], b1 = bias_sm[col + 1];
            float v00 = c[mt][nt][0] + b0, v01 = c[mt][nt][1] + b1;
            float v10 = c[mt][nt][2] + b0, v11 = c[mt][nt][3] + b1;
            if (nt < 8) {
                float2 p0, p1;
                p0.x = tf32r(v00 * 0.125f); p0.y = tf32r(v01 * 0.125f);
                p1.x = tf32r(v10 * 0.125f); p1.y = tf32r(v11 * 0.125f);
                *(float2*)(Pq + r0 * KP + col) = p0;
                *(float2*)(Pq + r1 * KP + col) = p1;
            } else if (nt < 16) {
                int d = col - 64;
                Kt[(d)     * KTP + r0] = tf32r(v00);
                Kt[(d + 1) * KTP + r0] = tf32r(v01);
                Kt[(d)     * KTP + r1] = tf32r(v10);
                Kt[(d + 1) * KTP + r1] = tf32r(v11);
            } else {
                int d = col - 128;
                float2 p0, p1;
                p0.x = tf32r(v00); p0.y = tf32r(v01);
                p1.x = tf32r(v10); p1.y = tf32r(v11);
                *(float2*)(Vs + r0 * VP + d) = p0;
                *(float2*)(Vs + r1 * VP + d) = p1;
            }
        }
    }
    __syncthreads();

    // ---- Phase 3: flash attention ----
    uint32_t qf[2][8][4];
#pragma unroll
    for (int mt = 0; mt < 2; mt++) {
        int rb = wq + mt * 16;
#pragma unroll
        for (int kt = 0; kt < 8; kt++) {
            int cc = kt * 8;
            qf[mt][kt][0] = __float_as_uint(Pq[(rb + gid)     * KP + cc + tig]);
            qf[mt][kt][1] = __float_as_uint(Pq[(rb + gid + 8) * KP + cc + tig]);
            qf[mt][kt][2] = __float_as_uint(Pq[(rb + gid)     * KP + cc + tig + 4]);
            qf[mt][kt][3] = __float_as_uint(Pq[(rb + gid + 8) * KP + cc + tig + 4]);
        }
    }
    __syncwarp();

    float o[2][8][4];
#pragma unroll
    for (int mt = 0; mt < 2; mt++)
#pragma unroll
        for (int nt = 0; nt < 8; nt++)
#pragma unroll
            for (int r = 0; r < 4; r++) o[mt][nt][r] = 0.f;

    float mrun[4], lrun[4];
#pragma unroll
    for (int z = 0; z < 4; z++) { mrun[z] = -1e30f; lrun[z] = 0.f; }

    for (int kb = 0; kb < 4; kb++) {
        const int kbase = kb * 64;

        float s[2][8][4];
#pragma unroll
        for (int mt = 0; mt < 2; mt++)
#pragma unroll
            for (int nt = 0; nt < 8; nt++)
#pragma unroll
                for (int r = 0; r < 4; r++) s[mt][nt][r] = 0.f;

        // S = Q K^T : b-frags from transposed Kt (conflict-free)
#pragma unroll
        for (int kt = 0; kt < 8; kt++) {
            const int cc = kt * 8;
#pragma unroll
            for (int nt = 0; nt < 8; nt++) {
                int key = kbase + nt * 8 + gid;
                uint32_t b0 = __float_as_uint(Kt[(cc + tig)     * KTP + key]);
                uint32_t b1 = __float_as_uint(Kt[(cc + tig + 4) * KTP + key]);
#pragma unroll
                for (int mt = 0; mt < 2; mt++)
                    mma_tf32(s[mt][nt][0], s[mt][nt][1], s[mt][nt][2], s[mt][nt][3],
                             qf[mt][kt][0], qf[mt][kt][1], qf[mt][kt][2], qf[mt][kt][3],
                             b0, b1);
            }
        }

        float mloc[4];
#pragma unroll
        for (int z = 0; z < 4; z++) mloc[z] = -1e30f;
#pragma unroll
        for (int mt = 0; mt < 2; mt++)
#pragma unroll
            for (int nt = 0; nt < 8; nt++) {
                mloc[mt * 2 + 0] = fmaxf(mloc[mt * 2 + 0], fmaxf(s[mt][nt][0], s[mt][nt][1]));
                mloc[mt * 2 + 1] = fmaxf(mloc[mt * 2 + 1], fmaxf(s[mt][nt][2], s[mt][nt][3]));
            }
#pragma unroll
        for (int z = 0; z < 4; z++) {
            mloc[z] = fmaxf(mloc[z], __shfl_xor_sync(0xffffffffu, mloc[z], 1));
            mloc[z] = fmaxf(mloc[z], __shfl_xor_sync(0xffffffffu, mloc[z], 2));
        }
        float scale[4], lsum[4];
#pragma unroll
        for (int z = 0; z < 4; z++) {
            float mnew = fmaxf(mrun[z], mloc[z]);
            scale[z] = __expf(mrun[z] - mnew);
            mrun[z] = mnew;
            lsum[z] = 0.f;
        }
#pragma unroll
        for (int mt = 0; mt < 2; mt++)
#pragma unroll
            for (int nt = 0; nt < 8; nt++) {
                s[mt][nt][0] = __expf(s[mt][nt][0] - mrun[mt * 2 + 0]);
                s[mt][nt][1] = __expf(s[mt][nt][1] - mrun[mt * 2 + 0]);
                s[mt][nt][2] = __expf(s[mt][nt][2] - mrun[mt * 2 + 1]);
                s[mt][nt][3] = __expf(s[mt][nt][3] - mrun[mt * 2 + 1]);
                lsum[mt * 2 + 0] += s[mt][nt][0] + s[mt][nt][1];
                lsum[mt * 2 + 1] += s[mt][nt][2] + s[mt][nt][3];
            }
#pragma unroll
        for (int z = 0; z < 4; z++) {
            lsum[z] += __shfl_xor_sync(0xffffffffu, lsum[z], 1);
            lsum[z] += __shfl_xor_sync(0xffffffffu, lsum[z], 2);
            lrun[z] = lrun[z] * scale[z] + lsum[z];
        }
#pragma unroll
        for (int mt = 0; mt < 2; mt++)
#pragma unroll
            for (int nt = 0; nt < 8; nt++) {
                o[mt][nt][0] *= scale[mt * 2 + 0];
                o[mt][nt][1] *= scale[mt * 2 + 0];
                o[mt][nt][2] *= scale[mt * 2 + 1];
                o[mt][nt][3] *= scale[mt * 2 + 1];
            }

        // P -> warp-private rows of Pq, reload as a-layout
        __syncwarp();
#pragma unroll
        for (int mt = 0; mt < 2; mt++) {
            int rb = wq + mt * 16;
#pragma unroll
            for (int nt = 0; nt < 8; nt++) {
                int col = nt * 8 + 2 * tig;
                float2 p0, p1;
                p0.x = tf32r(s[mt][nt][0]); p0.y = tf32r(s[mt][nt][1]);
                p1.x = tf32r(s[mt][nt][2]); p1.y = tf32r(s[mt][nt][3]);
                *(float2*)(Pq + (rb + gid)     * KP + col) = p0;
                *(float2*)(Pq + (rb + gid + 8) * KP + col) = p1;
            }
        }
        __syncwarp();
#pragma unroll
        for (int mt = 0; mt < 2; mt++) {
            int rb = wq + mt * 16;
#pragma unroll
            for (int kt = 0; kt < 8; kt++) {
                int cc = kt * 8;
                s[mt][kt][0] = Pq[(rb + gid)     * KP + cc + tig];
                s[mt][kt][1] = Pq[(rb + gid + 8) * KP + cc + tig];
                s[mt][kt][2] = Pq[(rb + gid)     * KP + cc + tig + 4];
                s[mt][kt][3] = Pq[(rb + gid + 8) * KP + cc + tig + 4];
            }
        }
        __syncwarp();

        // O += P V : b-frags from Vs (conflict-free)
#pragma unroll
        for (int kt = 0; kt < 8; kt++) {
#pragma unroll
            for (int nt = 0; nt < 8; nt++) {
                int dmc = nt * 8 + gid;
                uint32_t b0 = __float_as_uint(Vs[(kbase + kt * 8 + tig)     * VP + dmc]);
                uint32_t b1 = __float_as_uint(Vs[(kbase + kt * 8 + tig + 4) * VP + dmc]);
#pragma unroll
                for (int mt = 0; mt < 2; mt++)
                    mma_tf32(o[mt][nt][0], o[mt][nt][1], o[mt][nt][2], o[mt][nt][3],
                             __float_as_uint(s[mt][kt][0]), __float_as_uint(s[mt][kt][1]),
                             __float_as_uint(s[mt][kt][2]), __float_as_uint(s[mt][kt][3]),
                             b0, b1);
            }
        }
    }

    // ---- epilogue ----
    float inv[4];
#pragma unroll
    for (int z = 0; z < 4; z++) inv[z] = 1.f / lrun[z];

    const int b  = n >> 4;
    const int by = (n >> 2) & 3;
    const int bx = n & 3;

#pragma unroll
    for (int mt = 0; mt < 2; mt++) {
#pragma unroll
        for (int hh = 0; hh < 2; hh++) {
            int q = wq + mt * 16 + gid + 8 * hh;
            int f  = q >> 6;
            int ry = (q >> 3) & 7;
            int rx = q & 7;
            int gr = by * 8 + ry;
            int gc = bx * 8 + rx;
            int frame = pass + f;
            float* dst = outbuf + (((((size_t)b * 8 + frame) * 32 + gr) * 32 + gc) * CH) + h * DM;
            const float* res = g_xb + ((size_t)n * SEQ + q) * CH + h * DM;
            float sc = inv[mt * 2 + hh];
#pragma unroll
            for (int nt = 0; nt < 8; nt++) {
                int d = nt * 8 + 2 * tig;
                float2 r = *(const float2*)(res + d);
                float2 ov;
                ov.x = o[mt][nt][2 * hh + 0] * sc + r.x;
                ov.y = o[mt][nt][2 * hh + 1] * sc + r.y;
                *(float2*)(dst + d) = ov;
            }
        }
    }
}

// ---------------------------------------------------------------------------
extern "C" void kernel_launch(void* const* d_in, const int* in_sizes, int n_in,
                              void* d_out, int out_size)
{
    const float* x  = (const float*)d_in[0];
    const float* Wq = (const float*)d_in[1];
    const float* Wk = (const float*)d_in[2];
    const float* Wv = (const float*)d_in[3];
    const float* bq = (const float*)d_in[4];
    const float* bk = (const float*)d_in[5];
    const float* bv = (const float*)d_in[6];
    float* out = (float*)d_out;

    cudaFuncSetAttribute(fused_kernel, cudaFuncAttributeMaxDynamicSharedMemorySize,
                         FUSED_SMEM);

    wtrans_kernel<<<(3 * NH * CH * DM + 255) / 256, 256>>>(Wq, Wk, Wv);

    const int gather_blocks = (NWIN * SEQ * CH / 4 + 255) / 256;

    for (int pass = 0; pass <= 4; pass++) {
        gather_kernel<<<gather_blocks, 256>>>(x, out, pass);
        fused_kernel<<<NWIN * NH, 256, FUSED_SMEM>>>(out, pass, bq, bk, bv);
    }
}

// round 8
// speedup vs baseline: 5.6264x; 1.5815x over previous
#include <cuda_runtime.h>
#include <cuda_fp16.h>
#include <math.h>
#include <stdint.h>

// ---------------------------------------------------------------------------
// SpaceTimeLocalSelfAttention — R8: fused kernel on fp16 m16n8k16 mma
//   (fp16 mantissa == tf32 mantissa; half the MMA count and LDS traffic)
// B=4, T=8, H=W=32, C=512, NH=8, DM=64, KT=4, KS=8
// ---------------------------------------------------------------------------

#define NWIN   64
#define SEQ    256
#define CH     512
#define NH     8
#define DM     64
#define JC     192        // fused q|k|v columns per head

// smem pitches in 32-bit (half2) words
#define PQP    36         // Q/P slab: [row][d2 or key2]
#define KTP2   264        // Kt: [d2][key]
#define VP2    72         // V:  [key2][d]
#define SPA    20         // A staging pitch (16 half2 + 4 pad)
#define BPB    200        // B staging pitch (192 half2 + 8 pad)

#define PQ_W   (SEQ * PQP)            // 9216 words
#define KT_W   (32 * KTP2)            // 8448 words
#define VS_W   (128 * VP2)            // 9216 words
#define FUSED_SMEM ((PQ_W + KT_W + VS_W) * 4)   // 107520 B

__device__ float   g_xb[NWIN * SEQ * CH];               // fp32 (residual)
__device__ __half2 g_xh[NWIN * SEQ * CH / 2];           // fp16 copy (GEMM A)
__device__ __half2 g_wh[NH * (CH / 2) * JC];            // W packed half2-along-k

__device__ __forceinline__ uint32_t smem_u32(const void* p) {
    uint32_t a;
    asm("{ .reg .u64 t; cvta.to.shared.u64 t, %1; cvt.u32.u64 %0, t; }"
        : "=r"(a) : "l"(p));
    return a;
}

__device__ __forceinline__ void cp_async16(uint32_t dst, const void* src) {
    asm volatile("cp.async.cg.shared.global [%0], [%1], 16;"
                 :: "r"(dst), "l"(src) : "memory");
}

__device__ __forceinline__ void mma_f16(float& c0, float& c1, float& c2, float& c3,
                                        uint32_t a0, uint32_t a1, uint32_t a2, uint32_t a3,
                                        uint32_t b0, uint32_t b1)
{
    asm volatile(
        "mma.sync.aligned.m16n8k16.row.col.f32.f16.f16.f32 "
        "{%0,%1,%2,%3}, {%4,%5,%6,%7}, {%8,%9}, {%0,%1,%2,%3};"
        : "+f"(c0), "+f"(c1), "+f"(c2), "+f"(c3)
        : "r"(a0), "r"(a1), "r"(a2), "r"(a3), "r"(b0), "r"(b1));
}

__device__ __forceinline__ uint32_t pack_h2(float x, float y) {
    __half2 h = __float22half2_rn(make_float2(x, y));
    return *(uint32_t*)&h;
}

// ---------------------------------------------------------------------------
__global__ void wtrans_kernel(const float* __restrict__ Wq,
                              const float* __restrict__ Wk,
                              const float* __restrict__ Wv)
{
    int idx = blockIdx.x * blockDim.x + threadIdx.x;   // h*256*192 + k2*192 + j
    if (idx >= NH * (CH / 2) * JC) return;
    int j  = idx % JC;
    int k2 = (idx / JC) & (CH / 2 - 1);
    int h  = idx / (JC * (CH / 2));
    int w  = j >> 6;
    int dm = j & 63;
    const float* W = (w == 0) ? Wq : (w == 1) ? Wk : Wv;
    float v0 = W[((size_t)h * CH + 2 * k2)     * DM + dm];
    float v1 = W[((size_t)h * CH + 2 * k2 + 1) * DM + dm];
    g_wh[idx] = __float22half2_rn(make_float2(v0, v1));
}

// ---------------------------------------------------------------------------
__global__ void gather_kernel(const float* __restrict__ x,
                              const float* __restrict__ outbuf,
                              int pass)
{
    int idx = blockIdx.x * blockDim.x + threadIdx.x;
    if (idx >= (NWIN * SEQ * CH) / 4) return;
    int e = idx * 4;
    int c = e & (CH - 1);
    int s = (e >> 9) & (SEQ - 1);
    int n = e >> 17;
    int f  = s >> 6;
    int ry = (s >> 3) & 7;
    int rx = s & 7;
    int b  = n >> 4;
    int by = (n >> 2) & 3;
    int bx = n & 3;
    int gr = by * 8 + ry;
    int gc = bx * 8 + rx;

    const float* src;
    if (pass == 0) {
        src = x + (((((size_t)b * 8 + f) * 32 + gr) * 32 + gc) * CH + c);
    } else if (f < 3) {
        src = outbuf + (((((size_t)b * 8 + (pass + f)) * 32 + gr) * 32 + gc) * CH + c);
    } else {
        src = x + (((((size_t)b * 8 + (pass + 3)) * 32 + gr) * 32 + gc) * CH + c);
    }
    float4 v = *(const float4*)src;
    *(float4*)(g_xb + e) = v;
    g_xh[e / 2]     = __float22half2_rn(make_float2(v.x, v.y));
    g_xh[e / 2 + 1] = __float22half2_rn(make_float2(v.z, v.w));
}

// ---------------------------------------------------------------------------
// Fused: block = (n, h), 256 threads / 8 warps, fp16 mma, fp32 accum.
// ---------------------------------------------------------------------------
__global__ __launch_bounds__(256, 1) void fused_kernel(
    float* __restrict__ outbuf, int pass,
    const float* __restrict__ bq, const float* __restrict__ bk,
    const float* __restrict__ bv)
{
    const int n = blockIdx.x >> 3;
    const int h = blockIdx.x & 7;

    extern __shared__ __align__(16) uint32_t sm[];
    uint32_t* Pq  = sm;                 // [row][word 0..31] Q then P (pitch 36)
    uint32_t* Kth = sm + PQ_W;          // [d2][key] (pitch 264)
    uint32_t* Vh  = sm + PQ_W + KT_W;   // [key2][d] (pitch 72)
    __half*   Vhh = (__half*)Vh;
    // GEMM staging overlays (dead until phase 2):
    uint32_t* Asl[2] = { Pq, Pq + SEQ * SPA };                 // 2 x 5120 in Pq+Kt
    uint32_t* Bsl[2] = { Vh, Vh + 16 * BPB };                  // 2 x 3200 in Vh

    __shared__ float bias_sm[JC];

    const int tid = threadIdx.x;
    const int wid = tid >> 5;
    const int lane = tid & 31;
    const int gid = lane >> 2;
    const int tig = lane & 3;
    const int wq = wid * 32;

    if (tid < JC) {
        int dm = tid & 63;
        int wsel = tid >> 6;
        const float* bb = (wsel == 0) ? bq : (wsel == 1) ? bk : bv;
        bias_sm[tid] = bb[h * DM + dm];
    }

    const __half2* Abase = g_xh + (size_t)n * SEQ * (CH / 2);
    const __half2* Bbase = g_wh + (size_t)h * (CH / 2) * JC;

    float c[2][24][4];
#pragma unroll
    for (int mt = 0; mt < 2; mt++)
#pragma unroll
        for (int nt = 0; nt < 24; nt++)
#pragma unroll
            for (int r = 0; r < 4; r++) c[mt][nt][r] = 0.f;

    // ---- Phase 1: GEMM, 16 k-chunks of 32, double buffered ----
    // A: 256 rows x 16 half2/stage (4 x 16B chunks/thread)
    // B: 16 k2-rows x 192 half2/stage (3 x 16B chunks/thread)
    {
#pragma unroll
        for (int i = 0; i < 4; i++) {
            int chunk = tid + 256 * i;
            int row = chunk >> 2;
            int cg = chunk & 3;
            cp_async16(smem_u32(Asl[0] + row * SPA + cg * 4),
                       Abase + (size_t)row * (CH / 2) + cg * 4);
        }
#pragma unroll
        for (int i = 0; i < 3; i++) {
            int chunk = tid + 256 * i;
            int krow = chunk / 48;
            int cg = chunk % 48;
            cp_async16(smem_u32(Bsl[0] + krow * BPB + cg * 4),
                       Bbase + (size_t)krow * JC + cg * 4);
        }
        asm volatile("cp.async.commit_group;" ::: "memory");
    }

    for (int t = 0; t < 16; t++) {
        const int buf = t & 1;
        if (t < 15) {
            const int kc2 = (t + 1) * 16;      // half2 k offset
            const int nb = (t + 1) & 1;
#pragma unroll
            for (int i = 0; i < 4; i++) {
                int chunk = tid + 256 * i;
                int row = chunk >> 2;
                int cg = chunk & 3;
                cp_async16(smem_u32(Asl[nb] + row * SPA + cg * 4),
                           Abase + (size_t)row * (CH / 2) + kc2 + cg * 4);
            }
#pragma unroll
            for (int i = 0; i < 3; i++) {
                int chunk = tid + 256 * i;
                int krow = chunk / 48;
                int cg = chunk % 48;
                cp_async16(smem_u32(Bsl[nb] + krow * BPB + cg * 4),
                           Bbase + (size_t)(kc2 + krow) * JC + cg * 4);
            }
        }
        asm volatile("cp.async.commit_group;" ::: "memory");
        asm volatile("cp.async.wait_group 1;" ::: "memory");
        __syncthreads();

        const uint32_t* Ab = Asl[buf];
        const uint32_t* Bb = Bsl[buf];
#pragma unroll
        for (int k16 = 0; k16 < 2; k16++) {
            const int kw = k16 * 8;
            uint32_t af[2][4];
#pragma unroll
            for (int mt = 0; mt < 2; mt++) {
                int rb = wq + mt * 16;
                af[mt][0] = Ab[(rb + gid)     * SPA + kw + tig];
                af[mt][1] = Ab[(rb + gid + 8) * SPA + kw + tig];
                af[mt][2] = Ab[(rb + gid)     * SPA + kw + tig + 4];
                af[mt][3] = Ab[(rb + gid + 8) * SPA + kw + tig + 4];
            }
#pragma unroll
            for (int nt = 0; nt < 24; nt++) {
                int j = nt * 8 + gid;
                uint32_t b0 = Bb[(kw + tig)     * BPB + j];
                uint32_t b1 = Bb[(kw + tig + 4) * BPB + j];
#pragma unroll
                for (int mt = 0; mt < 2; mt++)
                    mma_f16(c[mt][nt][0], c[mt][nt][1], c[mt][nt][2], c[mt][nt][3],
                            af[mt][0], af[mt][1], af[mt][2], af[mt][3], b0, b1);
            }
        }
        __syncthreads();
    }

    // ---- Phase 2: Q(x0.125)->Pq, K->Kth (transposed), V->Vh (packed) ----
#pragma unroll
    for (int mt = 0; mt < 2; mt++) {
        int r0 = wq + mt * 16 + gid;
        int r1 = r0 + 8;
#pragma unroll
        for (int nt = 0; nt < 24; nt++) {
            int col = nt * 8 + 2 * tig;
            float b0 = bias_sm[col], b1 = bias_sm[col + 1];
            float v00 = c[mt][nt][0] + b0, v01 = c[mt][nt][1] + b1;
            float v10 = c[mt][nt][2] + b0, v11 = c[mt][nt][3] + b1;
            if (nt < 8) {
                int d2 = nt * 4 + tig;
                Pq[r0 * PQP + d2] = pack_h2(v00 * 0.125f, v01 * 0.125f);
                Pq[r1 * PQP + d2] = pack_h2(v10 * 0.125f, v11 * 0.125f);
            } else if (nt < 16) {
                int d2 = nt * 4 + tig - 32;
                Kth[d2 * KTP2 + r0] = pack_h2(v00, v01);
                Kth[d2 * KTP2 + r1] = pack_h2(v10, v11);
            } else {
                int d = col - 128;
                Vhh[(r0 >> 1) * 144 + 2 * d     + (r0 & 1)] = __float2half_rn(v00);
                Vhh[(r0 >> 1) * 144 + 2 * (d+1) + (r0 & 1)] = __float2half_rn(v01);
                Vhh[(r1 >> 1) * 144 + 2 * d     + (r1 & 1)] = __float2half_rn(v10);
                Vhh[(r1 >> 1) * 144 + 2 * (d+1) + (r1 & 1)] = __float2half_rn(v11);
            }
        }
    }
    __syncthreads();

    // ---- Phase 3: flash attention (fp16 mma) ----
    uint32_t qf[2][4][4];
#pragma unroll
    for (int mt = 0; mt < 2; mt++) {
        int rb = wq + mt * 16;
#pragma unroll
        for (int kt = 0; kt < 4; kt++) {
            int kw = kt * 8;
            qf[mt][kt][0] = Pq[(rb + gid)     * PQP + kw + tig];
            qf[mt][kt][1] = Pq[(rb + gid + 8) * PQP + kw + tig];
            qf[mt][kt][2] = Pq[(rb + gid)     * PQP + kw + tig + 4];
            qf[mt][kt][3] = Pq[(rb + gid + 8) * PQP + kw + tig + 4];
        }
    }
    __syncwarp();

    float o[2][8][4];
#pragma unroll
    for (int mt = 0; mt < 2; mt++)
#pragma unroll
        for (int nt = 0; nt < 8; nt++)
#pragma unroll
            for (int r = 0; r < 4; r++) o[mt][nt][r] = 0.f;

    float mrun[4], lrun[4];
#pragma unroll
    for (int z = 0; z < 4; z++) { mrun[z] = -1e30f; lrun[z] = 0.f; }

    for (int kb = 0; kb < 4; kb++) {
        const int kbase = kb * 64;

        float s[2][8][4];
#pragma unroll
        for (int mt = 0; mt < 2; mt++)
#pragma unroll
            for (int nt = 0; nt < 8; nt++)
#pragma unroll
                for (int r = 0; r < 4; r++) s[mt][nt][r] = 0.f;

        // S = Q K^T
#pragma unroll
        for (int kt = 0; kt < 4; kt++) {
            const int kw = kt * 8;
#pragma unroll
            for (int nt = 0; nt < 8; nt++) {
                int key = kbase + nt * 8 + gid;
                uint32_t b0 = Kth[(kw + tig)     * KTP2 + key];
                uint32_t b1 = Kth[(kw + tig + 4) * KTP2 + key];
#pragma unroll
                for (int mt = 0; mt < 2; mt++)
                    mma_f16(s[mt][nt][0], s[mt][nt][1], s[mt][nt][2], s[mt][nt][3],
                            qf[mt][kt][0], qf[mt][kt][1], qf[mt][kt][2], qf[mt][kt][3],
                            b0, b1);
            }
        }

        float mloc[4];
#pragma unroll
        for (int z = 0; z < 4; z++) mloc[z] = -1e30f;
#pragma unroll
        for (int mt = 0; mt < 2; mt++)
#pragma unroll
            for (int nt = 0; nt < 8; nt++) {
                mloc[mt * 2 + 0] = fmaxf(mloc[mt * 2 + 0], fmaxf(s[mt][nt][0], s[mt][nt][1]));
                mloc[mt * 2 + 1] = fmaxf(mloc[mt * 2 + 1], fmaxf(s[mt][nt][2], s[mt][nt][3]));
            }
#pragma unroll
        for (int z = 0; z < 4; z++) {
            mloc[z] = fmaxf(mloc[z], __shfl_xor_sync(0xffffffffu, mloc[z], 1));
            mloc[z] = fmaxf(mloc[z], __shfl_xor_sync(0xffffffffu, mloc[z], 2));
        }
        float scale[4], lsum[4];
#pragma unroll
        for (int z = 0; z < 4; z++) {
            float mnew = fmaxf(mrun[z], mloc[z]);
            scale[z] = __expf(mrun[z] - mnew);
            mrun[z] = mnew;
            lsum[z] = 0.f;
        }
#pragma unroll
        for (int mt = 0; mt < 2; mt++)
#pragma unroll
            for (int nt = 0; nt < 8; nt++) {
                s[mt][nt][0] = __expf(s[mt][nt][0] - mrun[mt * 2 + 0]);
                s[mt][nt][1] = __expf(s[mt][nt][1] - mrun[mt * 2 + 0]);
                s[mt][nt][2] = __expf(s[mt][nt][2] - mrun[mt * 2 + 1]);
                s[mt][nt][3] = __expf(s[mt][nt][3] - mrun[mt * 2 + 1]);
                lsum[mt * 2 + 0] += s[mt][nt][0] + s[mt][nt][1];
                lsum[mt * 2 + 1] += s[mt][nt][2] + s[mt][nt][3];
            }
#pragma unroll
        for (int z = 0; z < 4; z++) {
            lsum[z] += __shfl_xor_sync(0xffffffffu, lsum[z], 1);
            lsum[z] += __shfl_xor_sync(0xffffffffu, lsum[z], 2);
            lrun[z] = lrun[z] * scale[z] + lsum[z];
        }
#pragma unroll
        for (int mt = 0; mt < 2; mt++)
#pragma unroll
            for (int nt = 0; nt < 8; nt++) {
                o[mt][nt][0] *= scale[mt * 2 + 0];
                o[mt][nt][1] *= scale[mt * 2 + 0];
                o[mt][nt][2] *= scale[mt * 2 + 1];
                o[mt][nt][3] *= scale[mt * 2 + 1];
            }

        // P (fp16) -> warp-private rows of Pq, reload as a-frags
        __syncwarp();
#pragma unroll
        for (int mt = 0; mt < 2; mt++) {
            int rb = wq + mt * 16;
#pragma unroll
            for (int nt = 0; nt < 8; nt++) {
                int k2 = nt * 4 + tig;
                Pq[(rb + gid)     * PQP + k2] = pack_h2(s[mt][nt][0], s[mt][nt][1]);
                Pq[(rb + gid + 8) * PQP + k2] = pack_h2(s[mt][nt][2], s[mt][nt][3]);
            }
        }
        __syncwarp();
        uint32_t pf[2][4][4];
#pragma unroll
        for (int mt = 0; mt < 2; mt++) {
            int rb = wq + mt * 16;
#pragma unroll
            for (int kt = 0; kt < 4; kt++) {
                int kw = kt * 8;
                pf[mt][kt][0] = Pq[(rb + gid)     * PQP + kw + tig];
                pf[mt][kt][1] = Pq[(rb + gid + 8) * PQP + kw + tig];
                pf[mt][kt][2] = Pq[(rb + gid)     * PQP + kw + tig + 4];
                pf[mt][kt][3] = Pq[(rb + gid + 8) * PQP + kw + tig + 4];
            }
        }
        __syncwarp();

        // O += P V
#pragma unroll
        for (int kt = 0; kt < 4; kt++) {
            int kvb = kb * 32 + kt * 8;
#pragma unroll
            for (int nt = 0; nt < 8; nt++) {
                int d = nt * 8 + gid;
                uint32_t b0 = Vh[(kvb + tig)     * VP2 + d];
                uint32_t b1 = Vh[(kvb + tig + 4) * VP2 + d];
#pragma unroll
                for (int mt = 0; mt < 2; mt++)
                    mma_f16(o[mt][nt][0], o[mt][nt][1], o[mt][nt][2], o[mt][nt][3],
                            pf[mt][kt][0], pf[mt][kt][1], pf[mt][kt][2], pf[mt][kt][3],
                            b0, b1);
            }
        }
    }

    // ---- epilogue ----
    float inv[4];
#pragma unroll
    for (int z = 0; z < 4; z++) inv[z] = 1.f / lrun[z];

    const int b  = n >> 4;
    const int by = (n >> 2) & 3;
    const int bx = n & 3;

#pragma unroll
    for (int mt = 0; mt < 2; mt++) {
#pragma unroll
        for (int hh = 0; hh < 2; hh++) {
            int q = wq + mt * 16 + gid + 8 * hh;
            int f  = q >> 6;
            int ry = (q >> 3) & 7;
            int rx = q & 7;
            int gr = by * 8 + ry;
            int gc = bx * 8 + rx;
            int frame = pass + f;
            float* dst = outbuf + (((((size_t)b * 8 + frame) * 32 + gr) * 32 + gc) * CH) + h * DM;
            const float* res = g_xb + ((size_t)n * SEQ + q) * CH + h * DM;
            float sc = inv[mt * 2 + hh];
#pragma unroll
            for (int nt = 0; nt < 8; nt++) {
                int d = nt * 8 + 2 * tig;
                float2 r = *(const float2*)(res + d);
                float2 ov;
                ov.x = o[mt][nt][2 * hh + 0] * sc + r.x;
                ov.y = o[mt][nt][2 * hh + 1] * sc + r.y;
                *(float2*)(dst + d) = ov;
            }
        }
    }
}

// ---------------------------------------------------------------------------
extern "C" void kernel_launch(void* const* d_in, const int* in_sizes, int n_in,
                              void* d_out, int out_size)
{
    const float* x  = (const float*)d_in[0];
    const float* Wq = (const float*)d_in[1];
    const float* Wk = (const float*)d_in[2];
    const float* Wv = (const float*)d_in[3];
    const float* bq = (const float*)d_in[4];
    const float* bk = (const float*)d_in[5];
    const float* bv = (const float*)d_in[6];
    float* out = (float*)d_out;

    cudaFuncSetAttribute(fused_kernel, cudaFuncAttributeMaxDynamicSharedMemorySize,
                         FUSED_SMEM);

    wtrans_kernel<<<(NH * (CH / 2) * JC + 255) / 256, 256>>>(Wq, Wk, Wv);

    const int gather_blocks = (NWIN * SEQ * CH / 4 + 255) / 256;

    for (int pass = 0; pass <= 4; pass++) {
        gather_kernel<<<gather_blocks, 256>>>(x, out, pass);
        fused_kernel<<<NWIN * NH, 256, FUSED_SMEM>>>(out, pass, bq, bk, bv);
    }
}

// round 9
// speedup vs baseline: 6.1847x; 1.0992x over previous
#include <cuda_runtime.h>
#include <cuda_fp16.h>
#include <math.h>
#include <stdint.h>

// ---------------------------------------------------------------------------
// SpaceTimeLocalSelfAttention — R9: fused fp16 kernel, 512 threads + ldmatrix
// B=4, T=8, H=W=32, C=512, NH=8, DM=64, KT=4, KS=8
// ---------------------------------------------------------------------------

#define NWIN   64
#define SEQ    256
#define CH     512
#define NH     8
#define DM     64
#define JC     192

// attention smem pitches in 32-bit words
#define PQP    36         // Q/P slab [row][half2]
#define KTP2   264        // Kt [d2][key]
#define VP2    72         // V  [key2][d]

#define PQ_W   (SEQ * PQP)            // 9216
#define KT_W   (32 * KTP2)            // 8448
#define VS_W   (128 * VP2)            // 9216
#define FUSED_SMEM ((PQ_W + KT_W + VS_W) * 4)

// GEMM staging (overlays): pitch 20 words = 40 halves
#define ASTG_W (SEQ * 20)             // 5120 words per stage
#define BSTG_W (JC * 20)              // 3840 words per stage
#define BSTG_BASE (PQ_W + KT_W)       // B stages live in Vh region

__device__ float   g_xb[NWIN * SEQ * CH];
__device__ __half2 g_xh[NWIN * SEQ * CH / 2];
__device__ __half2 g_wh[NH * JC * (CH / 2)];   // [h][j][k2] n-major

__device__ __forceinline__ uint32_t smem_u32(const void* p) {
    uint32_t a;
    asm("{ .reg .u64 t; cvta.to.shared.u64 t, %1; cvt.u32.u64 %0, t; }"
        : "=r"(a) : "l"(p));
    return a;
}

__device__ __forceinline__ void cp_async16(uint32_t dst, const void* src) {
    asm volatile("cp.async.cg.shared.global [%0], [%1], 16;"
                 :: "r"(dst), "l"(src) : "memory");
}

__device__ __forceinline__ void ldmatrix_x4(uint32_t& r0, uint32_t& r1,
                                            uint32_t& r2, uint32_t& r3, uint32_t addr)
{
    asm volatile("ldmatrix.sync.aligned.m8n8.x4.shared.b16 {%0,%1,%2,%3}, [%4];"
                 : "=r"(r0), "=r"(r1), "=r"(r2), "=r"(r3) : "r"(addr));
}

__device__ __forceinline__ void mma_f16(float& c0, float& c1, float& c2, float& c3,
                                        uint32_t a0, uint32_t a1, uint32_t a2, uint32_t a3,
                                        uint32_t b0, uint32_t b1)
{
    asm volatile(
        "mma.sync.aligned.m16n8k16.row.col.f32.f16.f16.f32 "
        "{%0,%1,%2,%3}, {%4,%5,%6,%7}, {%8,%9}, {%0,%1,%2,%3};"
        : "+f"(c0), "+f"(c1), "+f"(c2), "+f"(c3)
        : "r"(a0), "r"(a1), "r"(a2), "r"(a3), "r"(b0), "r"(b1));
}

__device__ __forceinline__ uint32_t pack_h2(float x, float y) {
    __half2 h = __float22half2_rn(make_float2(x, y));
    return *(uint32_t*)&h;
}

// ---------------------------------------------------------------------------
__global__ void wtrans_kernel(const float* __restrict__ Wq,
                              const float* __restrict__ Wk,
                              const float* __restrict__ Wv)
{
    int idx = blockIdx.x * blockDim.x + threadIdx.x;   // h*JC*256 + j*256 + k2
    if (idx >= NH * JC * (CH / 2)) return;
    int k2 = idx & 255;
    int j  = (idx >> 8) % JC;
    int h  = idx / (JC * 256);
    int w  = j >> 6;
    int dm = j & 63;
    const float* W = (w == 0) ? Wq : (w == 1) ? Wk : Wv;
    float v0 = W[((size_t)h * CH + 2 * k2)     * DM + dm];
    float v1 = W[((size_t)h * CH + 2 * k2 + 1) * DM + dm];
    g_wh[idx] = __float22half2_rn(make_float2(v0, v1));
}

// ---------------------------------------------------------------------------
__global__ void gather_kernel(const float* __restrict__ x,
                              const float* __restrict__ outbuf,
                              int pass)
{
    int idx = blockIdx.x * blockDim.x + threadIdx.x;
    if (idx >= (NWIN * SEQ * CH) / 4) return;
    int e = idx * 4;
    int c = e & (CH - 1);
    int s = (e >> 9) & (SEQ - 1);
    int n = e >> 17;
    int f  = s >> 6;
    int ry = (s >> 3) & 7;
    int rx = s & 7;
    int b  = n >> 4;
    int by = (n >> 2) & 3;
    int bx = n & 3;
    int gr = by * 8 + ry;
    int gc = bx * 8 + rx;

    const float* src;
    if (pass == 0) {
        src = x + (((((size_t)b * 8 + f) * 32 + gr) * 32 + gc) * CH + c);
    } else if (f < 3) {
        src = outbuf + (((((size_t)b * 8 + (pass + f)) * 32 + gr) * 32 + gc) * CH + c);
    } else {
        src = x + (((((size_t)b * 8 + (pass + 3)) * 32 + gr) * 32 + gc) * CH + c);
    }
    float4 v = *(const float4*)src;
    *(float4*)(g_xb + e) = v;
    g_xh[e / 2]     = __float22half2_rn(make_float2(v.x, v.y));
    g_xh[e / 2 + 1] = __float22half2_rn(make_float2(v.z, v.w));
}

// ---------------------------------------------------------------------------
// Fused: block = (n, h), 512 threads / 16 warps.
// ---------------------------------------------------------------------------
__global__ __launch_bounds__(512, 1) void fused_kernel(
    float* __restrict__ outbuf, int pass,
    const float* __restrict__ bq, const float* __restrict__ bk,
    const float* __restrict__ bv)
{
    const int n = blockIdx.x >> 3;
    const int h = blockIdx.x & 7;

    extern __shared__ __align__(16) uint32_t sm[];
    uint32_t* Pq  = sm;                 // pitch PQP
    uint32_t* Kth = sm + PQ_W;          // pitch KTP2
    uint32_t* Vh  = sm + PQ_W + KT_W;   // pitch VP2
    __half*   Vhh = (__half*)Vh;

    __shared__ float bias_sm[JC];

    const int tid = threadIdx.x;
    const int wid = tid >> 5;           // 0..15
    const int lane = tid & 31;
    const int gid = lane >> 2;
    const int tig = lane & 3;
    const int wq = wid * 16;            // warp's 16 rows

    if (tid < JC) {
        int dm = tid & 63;
        int wsel = tid >> 6;
        const float* bb = (wsel == 0) ? bq : (wsel == 1) ? bk : bv;
        bias_sm[tid] = bb[h * DM + dm];
    }

    const __half2* Abase = g_xh + (size_t)n * SEQ * (CH / 2);
    const __half2* Bbase = g_wh + (size_t)h * JC * (CH / 2);

    const uint32_t smem_base = smem_u32(sm);
    // per-lane ldmatrix byte offsets (within a stage)
    const uint32_t a_off = (((wq + (lane & 15)) * 40) + ((lane >> 4) << 3)) * 2;
    const uint32_t b_off = ((((lane & 7) + ((lane >> 4) << 3)) * 40) +
                            (((lane >> 3) & 1) << 3)) * 2;
    const uint32_t Aaddr[2] = { smem_base + a_off,
                                smem_base + ASTG_W * 4 + a_off };
    const uint32_t Baddr[2] = { smem_base + BSTG_BASE * 4 + b_off,
                                smem_base + (BSTG_BASE + BSTG_W) * 4 + b_off };

    float c[24][4];
#pragma unroll
    for (int nt = 0; nt < 24; nt++)
#pragma unroll
        for (int r = 0; r < 4; r++) c[nt][r] = 0.f;

    // ---- Phase 1: GEMM, 16 k-chunks of 32 halves, double buffered ----
    // A: 1024 16B-chunks/stage; B: 768 chunks/stage.
    {
#pragma unroll
        for (int i = 0; i < 2; i++) {
            int ck = tid + 512 * i;
            int row = ck >> 2, cg = ck & 3;
            cp_async16(smem_base + (row * 20 + cg * 4) * 4,
                       Abase + (size_t)row * (CH / 2) + cg * 4);
        }
        for (int ck = tid; ck < 768; ck += 512) {
            int j = ck >> 2, cg = ck & 3;
            cp_async16(smem_base + (BSTG_BASE + j * 20 + cg * 4) * 4,
                       Bbase + (size_t)j * (CH / 2) + cg * 4);
        }
        asm volatile("cp.async.commit_group;" ::: "memory");
    }

    for (int t = 0; t < 16; t++) {
        const int buf = t & 1;
        if (t < 15) {
            const int kc2 = (t + 1) * 16;
            const int nb = (t + 1) & 1;
            const uint32_t abase = smem_base + nb * (ASTG_W * 4);
            const uint32_t bbase = smem_base + (BSTG_BASE + nb * BSTG_W) * 4;
#pragma unroll
            for (int i = 0; i < 2; i++) {
                int ck = tid + 512 * i;
                int row = ck >> 2, cg = ck & 3;
                cp_async16(abase + (row * 20 + cg * 4) * 4,
                           Abase + (size_t)row * (CH / 2) + kc2 + cg * 4);
            }
            for (int ck = tid; ck < 768; ck += 512) {
                int j = ck >> 2, cg = ck & 3;
                cp_async16(bbase + (j * 20 + cg * 4) * 4,
                           Bbase + (size_t)j * (CH / 2) + kc2 + cg * 4);
            }
        }
        asm volatile("cp.async.commit_group;" ::: "memory");
        asm volatile("cp.async.wait_group 1;" ::: "memory");
        __syncthreads();

#pragma unroll
        for (int k16 = 0; k16 < 2; k16++) {
            uint32_t a0, a1, a2, a3;
            ldmatrix_x4(a0, a1, a2, a3, Aaddr[buf] + k16 * 32);
#pragma unroll
            for (int pr = 0; pr < 12; pr++) {
                uint32_t b0, b1, b2, b3;
                ldmatrix_x4(b0, b1, b2, b3, Baddr[buf] + pr * 1280 + k16 * 32);
                mma_f16(c[2*pr][0], c[2*pr][1], c[2*pr][2], c[2*pr][3],
                        a0, a1, a2, a3, b0, b1);
                mma_f16(c[2*pr+1][0], c[2*pr+1][1], c[2*pr+1][2], c[2*pr+1][3],
                        a0, a1, a2, a3, b2, b3);
            }
        }
        __syncthreads();
    }

    // ---- Phase 2: Q(x0.125)->Pq, K->Kth (transposed), V->Vh ----
    {
        int r0 = wq + gid;
        int r1 = r0 + 8;
#pragma unroll
        for (int nt = 0; nt < 24; nt++) {
            int col = nt * 8 + 2 * tig;
            float b0 = bias_sm[col], b1 = bias_sm[col + 1];
            float v00 = c[nt][0] + b0, v01 = c[nt][1] + b1;
            float v10 = c[nt][2] + b0, v11 = c[nt][3] + b1;
            if (nt < 8) {
                int d2 = nt * 4 + tig;
                Pq[r0 * PQP + d2] = pack_h2(v00 * 0.125f, v01 * 0.125f);
                Pq[r1 * PQP + d2] = pack_h2(v10 * 0.125f, v11 * 0.125f);
            } else if (nt < 16) {
                int d2 = nt * 4 + tig - 32;
                Kth[d2 * KTP2 + r0] = pack_h2(v00, v01);
                Kth[d2 * KTP2 + r1] = pack_h2(v10, v11);
            } else {
                int d = col - 128;
                Vhh[(r0 >> 1) * 144 + 2 * d     + (r0 & 1)] = __float2half_rn(v00);
                Vhh[(r0 >> 1) * 144 + 2 * (d+1) + (r0 & 1)] = __float2half_rn(v01);
                Vhh[(r1 >> 1) * 144 + 2 * d     + (r1 & 1)] = __float2half_rn(v10);
                Vhh[(r1 >> 1) * 144 + 2 * (d+1) + (r1 & 1)] = __float2half_rn(v11);
            }
        }
    }
    __syncthreads();

    // ---- Phase 3: flash attention, 16 rows/warp ----
    uint32_t qf[4][4];
#pragma unroll
    for (int kt = 0; kt < 4; kt++) {
        int kw = kt * 8;
        qf[kt][0] = Pq[(wq + gid)     * PQP + kw + tig];
        qf[kt][1] = Pq[(wq + gid + 8) * PQP + kw + tig];
        qf[kt][2] = Pq[(wq + gid)     * PQP + kw + tig + 4];
        qf[kt][3] = Pq[(wq + gid + 8) * PQP + kw + tig + 4];
    }
    __syncwarp();

    float o[8][4];
#pragma unroll
    for (int nt = 0; nt < 8; nt++)
#pragma unroll
        for (int r = 0; r < 4; r++) o[nt][r] = 0.f;

    float mrun[2] = { -1e30f, -1e30f };
    float lrun[2] = { 0.f, 0.f };

    for (int kb = 0; kb < 4; kb++) {
        const int kbase = kb * 64;

        float s[8][4];
#pragma unroll
        for (int nt = 0; nt < 8; nt++)
#pragma unroll
            for (int r = 0; r < 4; r++) s[nt][r] = 0.f;

#pragma unroll
        for (int kt = 0; kt < 4; kt++) {
            const int kw = kt * 8;
#pragma unroll
            for (int nt = 0; nt < 8; nt++) {
                int key = kbase + nt * 8 + gid;
                uint32_t b0 = Kth[(kw + tig)     * KTP2 + key];
                uint32_t b1 = Kth[(kw + tig + 4) * KTP2 + key];
                mma_f16(s[nt][0], s[nt][1], s[nt][2], s[nt][3],
                        qf[kt][0], qf[kt][1], qf[kt][2], qf[kt][3], b0, b1);
            }
        }

        float mloc[2] = { -1e30f, -1e30f };
#pragma unroll
        for (int nt = 0; nt < 8; nt++) {
            mloc[0] = fmaxf(mloc[0], fmaxf(s[nt][0], s[nt][1]));
            mloc[1] = fmaxf(mloc[1], fmaxf(s[nt][2], s[nt][3]));
        }
#pragma unroll
        for (int z = 0; z < 2; z++) {
            mloc[z] = fmaxf(mloc[z], __shfl_xor_sync(0xffffffffu, mloc[z], 1));
            mloc[z] = fmaxf(mloc[z], __shfl_xor_sync(0xffffffffu, mloc[z], 2));
        }
        float scale[2], lsum[2];
#pragma unroll
        for (int z = 0; z < 2; z++) {
            float mnew = fmaxf(mrun[z], mloc[z]);
            scale[z] = __expf(mrun[z] - mnew);
            mrun[z] = mnew;
            lsum[z] = 0.f;
        }
#pragma unroll
        for (int nt = 0; nt < 8; nt++) {
            s[nt][0] = __expf(s[nt][0] - mrun[0]);
            s[nt][1] = __expf(s[nt][1] - mrun[0]);
            s[nt][2] = __expf(s[nt][2] - mrun[1]);
            s[nt][3] = __expf(s[nt][3] - mrun[1]);
            lsum[0] += s[nt][0] + s[nt][1];
            lsum[1] += s[nt][2] + s[nt][3];
        }
#pragma unroll
        for (int z = 0; z < 2; z++) {
            lsum[z] += __shfl_xor_sync(0xffffffffu, lsum[z], 1);
            lsum[z] += __shfl_xor_sync(0xffffffffu, lsum[z], 2);
            lrun[z] = lrun[z] * scale[z] + lsum[z];
        }
#pragma unroll
        for (int nt = 0; nt < 8; nt++) {
            o[nt][0] *= scale[0];
            o[nt][1] *= scale[0];
            o[nt][2] *= scale[1];
            o[nt][3] *= scale[1];
        }

        // P (fp16) -> warp-private rows of Pq, reload as a-frags
        __syncwarp();
#pragma unroll
        for (int nt = 0; nt < 8; nt++) {
            int k2 = nt * 4 + tig;
            Pq[(wq + gid)     * PQP + k2] = pack_h2(s[nt][0], s[nt][1]);
            Pq[(wq + gid + 8) * PQP + k2] = pack_h2(s[nt][2], s[nt][3]);
        }
        __syncwarp();
        uint32_t pf[4][4];
#pragma unroll
        for (int kt = 0; kt < 4; kt++) {
            int kw = kt * 8;
            pf[kt][0] = Pq[(wq + gid)     * PQP + kw + tig];
            pf[kt][1] = Pq[(wq + gid + 8) * PQP + kw + tig];
            pf[kt][2] = Pq[(wq + gid)     * PQP + kw + tig + 4];
            pf[kt][3] = Pq[(wq + gid + 8) * PQP + kw + tig + 4];
        }
        __syncwarp();

#pragma unroll
        for (int kt = 0; kt < 4; kt++) {
            int kvb = kb * 32 + kt * 8;
#pragma unroll
            for (int nt = 0; nt < 8; nt++) {
                int d = nt * 8 + gid;
                uint32_t b0 = Vh[(kvb + tig)     * VP2 + d];
                uint32_t b1 = Vh[(kvb + tig + 4) * VP2 + d];
                mma_f16(o[nt][0], o[nt][1], o[nt][2], o[nt][3],
                        pf[kt][0], pf[kt][1], pf[kt][2], pf[kt][3], b0, b1);
            }
        }
    }

    // ---- epilogue ----
    float inv[2] = { 1.f / lrun[0], 1.f / lrun[1] };

    const int b  = n >> 4;
    const int by = (n >> 2) & 3;
    const int bx = n & 3;

#pragma unroll
    for (int hh = 0; hh < 2; hh++) {
        int q = wq + gid + 8 * hh;
        int f  = q >> 6;
        int ry = (q >> 3) & 7;
        int rx = q & 7;
        int gr = by * 8 + ry;
        int gc = bx * 8 + rx;
        int frame = pass + f;
        float* dst = outbuf + (((((size_t)b * 8 + frame) * 32 + gr) * 32 + gc) * CH) + h * DM;
        const float* res = g_xb + ((size_t)n * SEQ + q) * CH + h * DM;
        float sc = inv[hh];
#pragma unroll
        for (int nt = 0; nt < 8; nt++) {
            int d = nt * 8 + 2 * tig;
            float2 r = *(const float2*)(res + d);
            float2 ov;
            ov.x = o[nt][2 * hh + 0] * sc + r.x;
            ov.y = o[nt][2 * hh + 1] * sc + r.y;
            *(float2*)(dst + d) = ov;
        }
    }
}

// ---------------------------------------------------------------------------
extern "C" void kernel_launch(void* const* d_in, const int* in_sizes, int n_in,
                              void* d_out, int out_size)
{
    const float* x  = (const float*)d_in[0];
    const float* Wq = (const float*)d_in[1];
    const float* Wk = (const float*)d_in[2];
    const float* Wv = (const float*)d_in[3];
    const float* bq = (const float*)d_in[4];
    const float* bk = (const float*)d_in[5];
    const float* bv = (const float*)d_in[6];
    float* out = (float*)d_out;

    cudaFuncSetAttribute(fused_kernel, cudaFuncAttributeMaxDynamicSharedMemorySize,
                         FUSED_SMEM);

    wtrans_kernel<<<(NH * JC * (CH / 2) + 255) / 256, 256>>>(Wq, Wk, Wv);

    const int gather_blocks = (NWIN * SEQ * CH / 4 + 255) / 256;

    for (int pass = 0; pass <= 4; pass++) {
        gather_kernel<<<gather_blocks, 256>>>(x, out, pass);
        fused_kernel<<<NWIN * NH, 512, FUSED_SMEM>>>(out, pass, bq, bk, bv);
    }
}

// round 11
// speedup vs baseline: 6.8328x; 1.1048x over previous
#include <cuda_runtime.h>
#include <cuda_fp16.h>
#include <math.h>
#include <stdint.h>

// ---------------------------------------------------------------------------
// SpaceTimeLocalSelfAttention — R11: R9 attention (proven) + 3-stage cp.async
//   GEMM pipeline + residual read direct from out/x (no fp32 xb scratch).
// B=4, T=8, H=W=32, C=512, NH=8, DM=64, KT=4, KS=8
// ---------------------------------------------------------------------------

#define NWIN   64
#define SEQ    256
#define CH     512
#define NH     8
#define DM     64
#define JC     192

// attention smem (32-bit words) — R9 layouts
#define PQP    36                    // Q/P slab pitch
#define KTP2   264                   // Kt [d2][key]
#define VP2    72                    // V  [key2][d]
#define PQ_W   (SEQ * PQP)           // 9216
#define KT_BASE PQ_W                 // 9216
#define KT_W   (32 * KTP2)           // 8448
#define VS_BASE (KT_BASE + KT_W)     // 17664
#define VS_W   (128 * VP2)           // 9216

// GEMM staging overlays (3 stages)
#define ASTG_W (SEQ * 20)            // 5120 words/stage
#define BSTG_W (JC * 20)             // 3840 words/stage
#define BSTG_BASE (3 * ASTG_W)       // 15360
#define FUSED_SMEM ((BSTG_BASE + 3 * BSTG_W) * 4)   // 107520 B

__device__ __half2 g_xh[NWIN * SEQ * CH / 2];
__device__ __half2 g_wh[NH * JC * (CH / 2)];   // [h][j][k2]

__device__ __forceinline__ uint32_t smem_u32(const void* p) {
    uint32_t a;
    asm("{ .reg .u64 t; cvta.to.shared.u64 t, %1; cvt.u32.u64 %0, t; }"
        : "=r"(a) : "l"(p));
    return a;
}
__device__ __forceinline__ void cp_async16(uint32_t dst, const void* src) {
    asm volatile("cp.async.cg.shared.global [%0], [%1], 16;"
                 :: "r"(dst), "l"(src) : "memory");
}
__device__ __forceinline__ void ldmatrix_x4(uint32_t& r0, uint32_t& r1,
                                            uint32_t& r2, uint32_t& r3, uint32_t addr)
{
    asm volatile("ldmatrix.sync.aligned.m8n8.x4.shared.b16 {%0,%1,%2,%3}, [%4];"
                 : "=r"(r0), "=r"(r1), "=r"(r2), "=r"(r3) : "r"(addr));
}
__device__ __forceinline__ void mma_f16(float& c0, float& c1, float& c2, float& c3,
                                        uint32_t a0, uint32_t a1, uint32_t a2, uint32_t a3,
                                        uint32_t b0, uint32_t b1)
{
    asm volatile(
        "mma.sync.aligned.m16n8k16.row.col.f32.f16.f16.f32 "
        "{%0,%1,%2,%3}, {%4,%5,%6,%7}, {%8,%9}, {%0,%1,%2,%3};"
        : "+f"(c0), "+f"(c1), "+f"(c2), "+f"(c3)
        : "r"(a0), "r"(a1), "r"(a2), "r"(a3), "r"(b0), "r"(b1));
}
__device__ __forceinline__ uint32_t pack_h2(float x, float y) {
    __half2 h = __float22half2_rn(make_float2(x, y));
    return *(uint32_t*)&h;
}

// ---------------------------------------------------------------------------
__global__ void wtrans_kernel(const float* __restrict__ Wq,
                              const float* __restrict__ Wk,
                              const float* __restrict__ Wv)
{
    int idx = blockIdx.x * blockDim.x + threadIdx.x;
    if (idx >= NH * JC * (CH / 2)) return;
    int k2 = idx & 255;
    int j  = (idx >> 8) % JC;
    int h  = idx / (JC * 256);
    int w  = j >> 6;
    int dm = j & 63;
    const float* W = (w == 0) ? Wq : (w == 1) ? Wk : Wv;
    float v0 = W[((size_t)h * CH + 2 * k2)     * DM + dm];
    float v1 = W[((size_t)h * CH + 2 * k2 + 1) * DM + dm];
    g_wh[idx] = __float22half2_rn(make_float2(v0, v1));
}

// ---------------------------------------------------------------------------
__global__ void gather_kernel(const float* __restrict__ x,
                              const float* __restrict__ outbuf,
                              int pass)
{
    int idx = blockIdx.x * blockDim.x + threadIdx.x;
    if (idx >= (NWIN * SEQ * CH) / 4) return;
    int e = idx * 4;
    int c = e & (CH - 1);
    int s = (e >> 9) & (SEQ - 1);
    int n = e >> 17;
    int f  = s >> 6;
    int ry = (s >> 3) & 7;
    int rx = s & 7;
    int b  = n >> 4;
    int by = (n >> 2) & 3;
    int bx = n & 3;
    int gr = by * 8 + ry;
    int gc = bx * 8 + rx;

    const float* src;
    if (pass == 0 || f == 3) {
        src = x + (((((size_t)b * 8 + (pass + f)) * 32 + gr) * 32 + gc) * CH + c);
    } else {
        src = outbuf + (((((size_t)b * 8 + (pass + f)) * 32 + gr) * 32 + gc) * CH + c);
    }
    float4 v = *(const float4*)src;
    g_xh[e / 2]     = __float22half2_rn(make_float2(v.x, v.y));
    g_xh[e / 2 + 1] = __float22half2_rn(make_float2(v.z, v.w));
}

// ---------------------------------------------------------------------------
__global__ __launch_bounds__(512, 1) void fused_kernel(
    float* __restrict__ outbuf, const float* __restrict__ xin, int pass,
    const float* __restrict__ bq, const float* __restrict__ bk,
    const float* __restrict__ bv)
{
    const int n = blockIdx.x >> 3;
    const int h = blockIdx.x & 7;

    extern __shared__ __align__(16) uint32_t sm[];
    uint32_t* Pq  = sm;                 // pitch PQP
    uint32_t* Kth = sm + KT_BASE;       // pitch KTP2
    uint32_t* Vh  = sm + VS_BASE;       // pitch VP2
    __half*   Vhh = (__half*)Vh;

    __shared__ float bias_sm[JC];

    const int tid = threadIdx.x;
    const int lane = tid & 31;
    const int gid = lane >> 2;
    const int tig = lane & 3;
    const int wid = tid >> 5;
    const int wq = wid * 16;

    if (tid < JC) {
        int dm = tid & 63;
        int wsel = tid >> 6;
        const float* bb = (wsel == 0) ? bq : (wsel == 1) ? bk : bv;
        bias_sm[tid] = bb[h * DM + dm];
    }

    const __half2* Abase = g_xh + (size_t)n * SEQ * (CH / 2);
    const __half2* Bbase = g_wh + (size_t)h * JC * (CH / 2);

    const uint32_t smem_base = smem_u32(sm);
    const uint32_t a_off = (((wq + (lane & 15)) * 40) + ((lane >> 4) << 3)) * 2;
    const uint32_t b_off = ((((lane & 7) + ((lane >> 4) << 3)) * 40) +
                            (((lane >> 3) & 1) << 3)) * 2;

    float c[24][4];
#pragma unroll
    for (int nt = 0; nt < 24; nt++)
#pragma unroll
        for (int r = 0; r < 4; r++) c[nt][r] = 0.f;

#define STAGE_LOAD(st, kc2)                                                     \
    {                                                                           \
        uint32_t ab = smem_base + (st) * (ASTG_W * 4);                          \
        _Pragma("unroll")                                                       \
        for (int i = 0; i < 2; i++) {                                           \
            int ck = tid + 512 * i;                                             \
            int row = ck >> 2, cg = ck & 3;                                     \
            cp_async16(ab + (row * 20 + cg * 4) * 4,                            \
                       Abase + (size_t)row * (CH / 2) + (kc2) + cg * 4);        \
        }                                                                       \
        uint32_t bb2 = smem_base + (BSTG_BASE + (st) * BSTG_W) * 4;             \
        for (int ck = tid; ck < 768; ck += 512) {                               \
            int j = ck >> 2, cg = ck & 3;                                       \
            cp_async16(bb2 + (j * 20 + cg * 4) * 4,                             \
                       Bbase + (size_t)j * (CH / 2) + (kc2) + cg * 4);          \
        }                                                                       \
    }

    // ---- Phase 1: GEMM, 16 k-chunks, 3-stage pipeline ----
    STAGE_LOAD(0, 0);
    asm volatile("cp.async.commit_group;" ::: "memory");
    STAGE_LOAD(1, 16);
    asm volatile("cp.async.commit_group;" ::: "memory");

    for (int t = 0; t < 16; t++) {
        asm volatile("cp.async.wait_group 1;" ::: "memory");
        __syncthreads();
        if (t < 14) {
            const int st = (t + 2) % 3;
            STAGE_LOAD(st, (t + 2) * 16);
        }
        asm volatile("cp.async.commit_group;" ::: "memory");

        const int buf = t % 3;
        const uint32_t Aaddr = smem_base + buf * (ASTG_W * 4) + a_off;
        const uint32_t Baddr = smem_base + (BSTG_BASE + buf * BSTG_W) * 4 + b_off;
#pragma unroll
        for (int k16 = 0; k16 < 2; k16++) {
            uint32_t a0, a1, a2, a3;
            ldmatrix_x4(a0, a1, a2, a3, Aaddr + k16 * 32);
#pragma unroll
            for (int pr = 0; pr < 12; pr++) {
                uint32_t b0, b1, b2, b3;
                ldmatrix_x4(b0, b1, b2, b3, Baddr + pr * 1280 + k16 * 32);
                mma_f16(c[2*pr][0], c[2*pr][1], c[2*pr][2], c[2*pr][3],
                        a0, a1, a2, a3, b0, b1);
                mma_f16(c[2*pr+1][0], c[2*pr+1][1], c[2*pr+1][2], c[2*pr+1][3],
                        a0, a1, a2, a3, b2, b3);
            }
        }
        __syncthreads();
    }

    // ---- Phase 2: Q(x0.125)->Pq, K->Kth [d2][key], V->Vh [key2][d] (R9) ----
    {
        int r0 = wq + gid;
        int r1 = r0 + 8;
#pragma unroll
        for (int nt = 0; nt < 24; nt++) {
            int col = nt * 8 + 2 * tig;
            float b0 = bias_sm[col], b1 = bias_sm[col + 1];
            float v00 = c[nt][0] + b0, v01 = c[nt][1] + b1;
            float v10 = c[nt][2] + b0, v11 = c[nt][3] + b1;
            if (nt < 8) {
                int d2 = nt * 4 + tig;
                Pq[r0 * PQP + d2] = pack_h2(v00 * 0.125f, v01 * 0.125f);
                Pq[r1 * PQP + d2] = pack_h2(v10 * 0.125f, v11 * 0.125f);
            } else if (nt < 16) {
                int d2 = nt * 4 + tig - 32;
                Kth[d2 * KTP2 + r0] = pack_h2(v00, v01);
                Kth[d2 * KTP2 + r1] = pack_h2(v10, v11);
            } else {
                int d = col - 128;
                Vhh[(r0 >> 1) * 144 + 2 * d     + (r0 & 1)] = __float2half_rn(v00);
                Vhh[(r0 >> 1) * 144 + 2 * (d+1) + (r0 & 1)] = __float2half_rn(v01);
                Vhh[(r1 >> 1) * 144 + 2 * d     + (r1 & 1)] = __float2half_rn(v10);
                Vhh[(r1 >> 1) * 144 + 2 * (d+1) + (r1 & 1)] = __float2half_rn(v11);
            }
        }
    }
    __syncthreads();

    // ---- Phase 3: flash attention (R9 scalar-LDS layouts, proven) ----
    uint32_t qf[4][4];
#pragma unroll
    for (int kt = 0; kt < 4; kt++) {
        int kw = kt * 8;
        qf[kt][0] = Pq[(wq + gid)     * PQP + kw + tig];
        qf[kt][1] = Pq[(wq + gid + 8) * PQP + kw + tig];
        qf[kt][2] = Pq[(wq + gid)     * PQP + kw + tig + 4];
        qf[kt][3] = Pq[(wq + gid + 8) * PQP + kw + tig + 4];
    }
    __syncwarp();

    float o[8][4];
#pragma unroll
    for (int nt = 0; nt < 8; nt++)
#pragma unroll
        for (int r = 0; r < 4; r++) o[nt][r] = 0.f;

    float mrun[2] = { -1e30f, -1e30f };
    float lrun[2] = { 0.f, 0.f };

    for (int kb = 0; kb < 4; kb++) {
        const int kbase = kb * 64;

        float s[8][4];
#pragma unroll
        for (int nt = 0; nt < 8; nt++)
#pragma unroll
            for (int r = 0; r < 4; r++) s[nt][r] = 0.f;

#pragma unroll
        for (int kt = 0; kt < 4; kt++) {
            const int kw = kt * 8;
#pragma unroll
            for (int nt = 0; nt < 8; nt++) {
                int key = kbase + nt * 8 + gid;
                uint32_t b0 = Kth[(kw + tig)     * KTP2 + key];
                uint32_t b1 = Kth[(kw + tig + 4) * KTP2 + key];
                mma_f16(s[nt][0], s[nt][1], s[nt][2], s[nt][3],
                        qf[kt][0], qf[kt][1], qf[kt][2], qf[kt][3], b0, b1);
            }
        }

        float mloc[2] = { -1e30f, -1e30f };
#pragma unroll
        for (int nt = 0; nt < 8; nt++) {
            mloc[0] = fmaxf(mloc[0], fmaxf(s[nt][0], s[nt][1]));
            mloc[1] = fmaxf(mloc[1], fmaxf(s[nt][2], s[nt][3]));
        }
#pragma unroll
        for (int z = 0; z < 2; z++) {
            mloc[z] = fmaxf(mloc[z], __shfl_xor_sync(0xffffffffu, mloc[z], 1));
            mloc[z] = fmaxf(mloc[z], __shfl_xor_sync(0xffffffffu, mloc[z], 2));
        }
        float scale[2], lsum[2];
#pragma unroll
        for (int z = 0; z < 2; z++) {
            float mnew = fmaxf(mrun[z], mloc[z]);
            scale[z] = __expf(mrun[z] - mnew);
            mrun[z] = mnew;
            lsum[z] = 0.f;
        }
#pragma unroll
        for (int nt = 0; nt < 8; nt++) {
            s[nt][0] = __expf(s[nt][0] - mrun[0]);
            s[nt][1] = __expf(s[nt][1] - mrun[0]);
            s[nt][2] = __expf(s[nt][2] - mrun[1]);
            s[nt][3] = __expf(s[nt][3] - mrun[1]);
            lsum[0] += s[nt][0] + s[nt][1];
            lsum[1] += s[nt][2] + s[nt][3];
        }
#pragma unroll
        for (int z = 0; z < 2; z++) {
            lsum[z] += __shfl_xor_sync(0xffffffffu, lsum[z], 1);
            lsum[z] += __shfl_xor_sync(0xffffffffu, lsum[z], 2);
            lrun[z] = lrun[z] * scale[z] + lsum[z];
        }
#pragma unroll
        for (int nt = 0; nt < 8; nt++) {
            o[nt][0] *= scale[0];
            o[nt][1] *= scale[0];
            o[nt][2] *= scale[1];
            o[nt][3] *= scale[1];
        }

        __syncwarp();
#pragma unroll
        for (int nt = 0; nt < 8; nt++) {
            int k2 = nt * 4 + tig;
            Pq[(wq + gid)     * PQP + k2] = pack_h2(s[nt][0], s[nt][1]);
            Pq[(wq + gid + 8) * PQP + k2] = pack_h2(s[nt][2], s[nt][3]);
        }
        __syncwarp();
        uint32_t pf[4][4];
#pragma unroll
        for (int kt = 0; kt < 4; kt++) {
            int kw = kt * 8;
            pf[kt][0] = Pq[(wq + gid)     * PQP + kw + tig];
            pf[kt][1] = Pq[(wq + gid + 8) * PQP + kw + tig];
            pf[kt][2] = Pq[(wq + gid)     * PQP + kw + tig + 4];
            pf[kt][3] = Pq[(wq + gid + 8) * PQP + kw + tig + 4];
        }
        __syncwarp();

#pragma unroll
        for (int kt = 0; kt < 4; kt++) {
            int kvb = kb * 32 + kt * 8;
#pragma unroll
            for (int nt = 0; nt < 8; nt++) {
                int d = nt * 8 + gid;
                uint32_t b0 = Vh[(kvb + tig)     * VP2 + d];
                uint32_t b1 = Vh[(kvb + tig + 4) * VP2 + d];
                mma_f16(o[nt][0], o[nt][1], o[nt][2], o[nt][3],
                        pf[kt][0], pf[kt][1], pf[kt][2], pf[kt][3], b0, b1);
            }
        }
    }

    // ---- epilogue: normalize, residual (direct from out/x), scatter ----
    float inv[2] = { 1.f / lrun[0], 1.f / lrun[1] };

    const int b  = n >> 4;
    const int by = (n >> 2) & 3;
    const int bx = n & 3;

#pragma unroll
    for (int hh = 0; hh < 2; hh++) {
        int q = wq + gid + 8 * hh;
        int f  = q >> 6;
        int ry = (q >> 3) & 7;
        int rx = q & 7;
        int gr = by * 8 + ry;
        int gc = bx * 8 + rx;
        int frame = pass + f;
        size_t rowoff = (((((size_t)b * 8 + frame) * 32 + gr) * 32 + gc) * CH) + h * DM;
        const float* res = ((pass == 0 || f == 3) ? xin : (const float*)outbuf) + rowoff;
        float* dst = outbuf + rowoff;
        float sc = inv[hh];
#pragma unroll
        for (int nt = 0; nt < 8; nt++) {
            int d = nt * 8 + 2 * tig;
            float2 r = *(const float2*)(res + d);
            float2 ov;
            ov.x = o[nt][2 * hh + 0] * sc + r.x;
            ov.y = o[nt][2 * hh + 1] * sc + r.y;
            *(float2*)(dst + d) = ov;
        }
    }
}

// ---------------------------------------------------------------------------
extern "C" void kernel_launch(void* const* d_in, const int* in_sizes, int n_in,
                              void* d_out, int out_size)
{
    const float* x  = (const float*)d_in[0];
    const float* Wq = (const float*)d_in[1];
    const float* Wk = (const float*)d_in[2];
    const float* Wv = (const float*)d_in[3];
    const float* bq = (const float*)d_in[4];
    const float* bk = (const float*)d_in[5];
    const float* bv = (const float*)d_in[6];
    float* out = (float*)d_out;

    cudaFuncSetAttribute(fused_kernel, cudaFuncAttributeMaxDynamicSharedMemorySize,
                         FUSED_SMEM);

    wtrans_kernel<<<(NH * JC * (CH / 2) + 255) / 256, 256>>>(Wq, Wk, Wv);

    const int gather_blocks = (NWIN * SEQ * CH / 4 + 255) / 256;

    for (int pass = 0; pass <= 4; pass++) {
        gather_kernel<<<gather_blocks, 256>>>(x, out, pass);
        fused_kernel<<<NWIN * NH, 512, FUSED_SMEM>>>(out, x, pass, bq, bk, bv);
    }
}